// round 5
// baseline (speedup 1.0000x reference)
#include <cuda_runtime.h>
#include <cuda_bf16.h>
#include <math.h>
#include <stdint.h>

// Problem constants
#define NN 30000      // nodes
#define EE 150000     // edges per graph
#define IND 512
#define HIDD 512
#define OUTD 256
#define GG 3
#define CONCAT (HIDD * GG)   // 1536

// ============================================================================
// Scratch (device globals)
// ============================================================================
__device__ __nv_bfloat16 g_AXhi[(size_t)GG * NN * IND];  // aggregated, scaled X (hi)
__device__ __nv_bfloat16 g_AXlo[(size_t)GG * NN * IND];  // (lo)
__device__ __nv_bfloat16 g_Hhi[(size_t)NN * CONCAT];
__device__ __nv_bfloat16 g_Hlo[(size_t)NN * CONCAT];
__device__ __nv_bfloat16 g_Bthi[(size_t)CONCAT * IND];   // [W0|W1|W2]^T : row n, col k
__device__ __nv_bfloat16 g_Btlo[(size_t)CONCAT * IND];
__device__ __nv_bfloat16 g_BtLhi[(size_t)OUTD * CONCAT]; // W_lin^T : row n, col k
__device__ __nv_bfloat16 g_BtLlo[(size_t)OUTD * CONCAT];
__device__ int   g_deg_in [GG * NN];
__device__ int   g_deg_out[GG * NN];
__device__ int   g_off    [GG * (NN + 1)];
__device__ int   g_cursor [GG * NN];
__device__ int   g_csr_src[GG * EE];
__device__ float g_alpha  [GG];

// ============================================================================
// PTX helpers (all plain-sm_103-legal: cp.async / ldmatrix / mma.sync)
// ============================================================================
__device__ __forceinline__ uint32_t smem_to_u32(const void* p) {
    uint32_t a;
    asm("{ .reg .u64 t; cvta.to.shared.u64 t, %1; cvt.u32.u64 %0, t; }" : "=r"(a) : "l"(p));
    return a;
}
#define CP16(dst32, src) \
    asm volatile("cp.async.cg.shared.global [%0], [%1], 16;" :: "r"(dst32), "l"(src))
#define CP_COMMIT() asm volatile("cp.async.commit_group;" ::: "memory")
#define CP_WAIT(n)  asm volatile("cp.async.wait_group %0;" :: "n"(n) : "memory")

#define LDSM_X4(r0, r1, r2, r3, addr) \
    asm volatile("ldmatrix.sync.aligned.m8n8.x4.shared.b16 {%0,%1,%2,%3}, [%4];" \
        : "=r"(r0), "=r"(r1), "=r"(r2), "=r"(r3) : "r"(addr))

#define MMA_BF16(c, a, b) \
    asm volatile("mma.sync.aligned.m16n8k16.row.col.f32.bf16.bf16.f32 " \
        "{%0,%1,%2,%3}, {%4,%5,%6,%7}, {%8,%9}, {%0,%1,%2,%3};" \
        : "+f"((c)[0]), "+f"((c)[1]), "+f"((c)[2]), "+f"((c)[3]) \
        : "r"((a)[0]), "r"((a)[1]), "r"((a)[2]), "r"((a)[3]), "r"((b)[0]), "r"((b)[1]))

// ============================================================================
// Setup kernels
// ============================================================================
__global__ void zero_kernel(const float* __restrict__ alphas) {
    int i = blockIdx.x * blockDim.x + threadIdx.x;
    int total = 2 * GG * NN;
    for (int idx = i; idx < total; idx += gridDim.x * blockDim.x) {
        if (idx < GG * NN) g_deg_in[idx] = 0;
        else               g_deg_out[idx - GG * NN] = 0;
    }
    if (blockIdx.x == 0 && threadIdx.x == 0) {
        float m = alphas[0];
        for (int g = 1; g < GG; g++) m = fmaxf(m, alphas[g]);
        float s = 0.f, e[GG];
        for (int g = 0; g < GG; g++) { e[g] = expf(alphas[g] - m); s += e[g]; }
        for (int g = 0; g < GG; g++) g_alpha[g] = e[g] / s;
    }
}

__global__ void hist_kernel(const int* __restrict__ e0, const int* __restrict__ e1,
                            const int* __restrict__ e2) {
    int i = blockIdx.x * blockDim.x + threadIdx.x;
    if (i >= GG * EE) return;
    int g = i / EE, idx = i - g * EE;
    const int* e = (g == 0) ? e0 : (g == 1) ? e1 : e2;
    atomicAdd(&g_deg_out[g * NN + e[idx]], 1);
    atomicAdd(&g_deg_in [g * NN + e[EE + idx]], 1);
}

__global__ void scan_kernel() {
    int g = blockIdx.x;
    const int* cnt = g_deg_in + g * NN;
    int* off = g_off + g * (NN + 1);
    int* cur = g_cursor + g * NN;
    __shared__ int sh[1024];
    int carry = 0;
    for (int base = 0; base < NN; base += 1024) {
        int i = base + threadIdx.x;
        int v = (i < NN) ? cnt[i] : 0;
        sh[threadIdx.x] = v;
        __syncthreads();
        #pragma unroll
        for (int s = 1; s < 1024; s <<= 1) {
            int t = (threadIdx.x >= s) ? sh[threadIdx.x - s] : 0;
            __syncthreads();
            sh[threadIdx.x] += t;
            __syncthreads();
        }
        int incl = sh[threadIdx.x];
        if (i < NN) { off[i] = carry + incl - v; cur[i] = carry + incl - v; }
        carry += sh[1023];
        __syncthreads();
    }
    if (threadIdx.x == 0) off[NN] = carry;
}

__global__ void fill_kernel(const int* __restrict__ e0, const int* __restrict__ e1,
                            const int* __restrict__ e2) {
    int i = blockIdx.x * blockDim.x + threadIdx.x;
    if (i >= GG * EE) return;
    int g = i / EE, idx = i - g * EE;
    const int* e = (g == 0) ? e0 : (g == 1) ? e1 : e2;
    int src = e[idx];
    int dst = e[EE + idx];
    int p = atomicAdd(&g_cursor[g * NN + dst], 1);
    g_csr_src[g * EE + p] = src;
}

// ============================================================================
// fp32 -> bf16 hi/lo split conversions (weights)
// ============================================================================
__device__ __forceinline__ void split_bf16(float v, __nv_bfloat16& hi, __nv_bfloat16& lo) {
    hi = __float2bfloat16(v);
    lo = __float2bfloat16(v - __bfloat162float(hi));
}

__global__ void conv_w_kernel(const float* __restrict__ W0, const float* __restrict__ W1,
                              const float* __restrict__ W2) {
    int i = blockIdx.x * blockDim.x + threadIdx.x;
    int total = GG * IND * HIDD;
    for (int idx = i; idx < total; idx += gridDim.x * blockDim.x) {
        int g = idx >> 18;
        int r = idx & 262143;
        int k = r >> 9;
        int n = r & 511;
        const float* W = (g == 0) ? W0 : (g == 1) ? W1 : W2;
        __nv_bfloat16 h, l;
        split_bf16(W[k * HIDD + n], h, l);
        size_t o = (size_t)(g * HIDD + n) * IND + k;
        g_Bthi[o] = h; g_Btlo[o] = l;
    }
}

__global__ void conv_wlin_kernel(const float* __restrict__ WL) {
    int i = blockIdx.x * blockDim.x + threadIdx.x;
    int total = CONCAT * OUTD;
    for (int idx = i; idx < total; idx += gridDim.x * blockDim.x) {
        int k = idx >> 8;
        int n = idx & 255;
        __nv_bfloat16 h, l;
        split_bf16(WL[idx], h, l);
        size_t o = (size_t)n * CONCAT + k;
        g_BtLhi[o] = h; g_BtLlo[o] = l;
    }
}

// ============================================================================
// Pre-GEMM aggregation on X (linearity: (rsqrt_in * segsum(x*rsqrt_out)) @ W).
// AX[g][dst] = rsqrt(deg_in[dst]) * sum_{e->dst} x[src] * rsqrt(deg_out[src])
// X (61MB) is L2-resident -> gather runs at LTS cap. Output split to bf16 hi/lo.
// grid = (NN, GG), 128 threads, 4 cols/thread.
// ============================================================================
__global__ void __launch_bounds__(128)
agg_x_kernel(const float* __restrict__ x) {
    int dst = blockIdx.x;
    int g = blockIdx.y;
    int c = threadIdx.x * 4;

    int beg = g_off[g * (NN + 1) + dst];
    int end = g_off[g * (NN + 1) + dst + 1];
    const int* srcs = g_csr_src + g * EE;
    const int* dout = g_deg_out + g * NN;

    float4 acc = make_float4(0.f, 0.f, 0.f, 0.f);
    for (int e = beg; e < end; e++) {
        int s = srcs[e];
        int d = dout[s];
        float so = rsqrtf((float)(d > 1 ? d : 1));
        float4 v = *(const float4*)(x + (size_t)s * IND + c);
        acc.x += v.x * so; acc.y += v.y * so; acc.z += v.z * so; acc.w += v.w * so;
    }

    int di = g_deg_in[g * NN + dst];
    float rsv = rsqrtf((float)(di > 1 ? di : 1));
    acc.x *= rsv; acc.y *= rsv; acc.z *= rsv; acc.w *= rsv;

    size_t base = ((size_t)g * NN + dst) * IND + c;
    __nv_bfloat16 hi[4], lo[4];
    split_bf16(acc.x, hi[0], lo[0]); split_bf16(acc.y, hi[1], lo[1]);
    split_bf16(acc.z, hi[2], lo[2]); split_bf16(acc.w, hi[3], lo[3]);
    *(__nv_bfloat162*)(g_AXhi + base)     = __halves2bfloat162(hi[0], hi[1]);
    *(__nv_bfloat162*)(g_AXhi + base + 2) = __halves2bfloat162(hi[2], hi[3]);
    *(__nv_bfloat162*)(g_AXlo + base)     = __halves2bfloat162(lo[0], lo[1]);
    *(__nv_bfloat162*)(g_AXlo + base + 2) = __halves2bfloat162(lo[2], lo[3]);
}

// ============================================================================
// bf16x3 GEMM via mma.sync. CTA tile 128x128, BK=64, 256 threads (8 warps,
// 2x4, warp tile 64x32), cp.async double-buffered SMEM, swizzled ldmatrix.
// mode 1 (per graph g): A=g_AX[g] (K=512), B=g_Bt[g],
//        epilogue tanh(alpha_g*(D+b_g)) -> Hhi/Hlo cols [g*512, (g+1)*512)
// mode 2: A=g_H (K=1536), B=g_BtL, C=outp (ldc=256), +bias
// ============================================================================
#define BUF_BYTES 65536
#define GSMEM_TOTAL (1024 + 2 * BUF_BYTES)

__device__ __forceinline__ void prefetch_chunk(uint32_t sdst,
        const __nv_bfloat16* __restrict__ Ahi, const __nv_bfloat16* __restrict__ Alo,
        const __nv_bfloat16* __restrict__ Bhi, const __nv_bfloat16* __restrict__ Blo,
        int kc, int m0, int n0, int K, int tid) {
    int row = tid >> 1;
    int cb = (tid & 1) * 4;
    int mrow = m0 + row; if (mrow >= NN) mrow = NN - 1;   // clamped rows never stored
    int nrow = n0 + row;
    const char* pAh = (const char*)(Ahi + (size_t)mrow * K) + kc * 128;
    const char* pAl = (const char*)(Alo + (size_t)mrow * K) + kc * 128;
    const char* pBh = (const char*)(Bhi + (size_t)nrow * K) + kc * 128;
    const char* pBl = (const char*)(Blo + (size_t)nrow * K) + kc * 128;
    #pragma unroll
    for (int q = 0; q < 4; q++) {
        int col = (cb + q) * 16;
        uint32_t swz = ((uint32_t)(row * 128 + col)) ^ ((uint32_t)(row & 7) << 4);
        CP16(sdst + swz,                 pAh + col);
        CP16(sdst + 16384 + swz,         pAl + col);
        CP16(sdst + 32768 + swz,         pBh + col);
        CP16(sdst + 49152 + swz,         pBl + col);
    }
}

__global__ void __launch_bounds__(256, 1)
mma_gemm_kernel(float* outp, const float* __restrict__ bias, int mode, int K, int g) {
    extern __shared__ char smem_raw[];
    uint32_t sb0 = smem_to_u32(smem_raw);
    uint32_t sb = (sb0 + 1023) & ~1023u;

    const __nv_bfloat16 *Ahi, *Alo, *Bhi, *Blo;
    if (mode == 1) {
        Ahi = g_AXhi + (size_t)g * NN * IND;  Alo = g_AXlo + (size_t)g * NN * IND;
        Bhi = g_Bthi + (size_t)g * HIDD * IND; Blo = g_Btlo + (size_t)g * HIDD * IND;
    } else {
        Ahi = g_Hhi; Alo = g_Hlo; Bhi = g_BtLhi; Blo = g_BtLlo;
    }

    int tid = threadIdx.x;
    int lane = tid & 31, wid = tid >> 5;
    int warpM = wid >> 2, warpN = wid & 3;
    int n0 = blockIdx.x * 128;
    int m0 = blockIdx.y * 128;

    float acc[4][4][4];
    #pragma unroll
    for (int i = 0; i < 4; i++)
        #pragma unroll
        for (int j = 0; j < 4; j++)
            #pragma unroll
            for (int r = 0; r < 4; r++) acc[i][j][r] = 0.f;

    int aRow = warpM * 64 + (lane & 15);
    int aCol = (lane >> 4) * 16;
    int bRow = warpN * 32 + (lane & 7) + (lane >> 4) * 8;
    int bCol = ((lane >> 3) & 1) * 16;

    int nk = K >> 6;
    prefetch_chunk(sb, Ahi, Alo, Bhi, Blo, 0, m0, n0, K, tid);
    CP_COMMIT();

    int buf = 0;
    for (int kc = 0; kc < nk; kc++) {
        if (kc + 1 < nk) {
            prefetch_chunk(sb + (buf ^ 1) * BUF_BYTES, Ahi, Alo, Bhi, Blo,
                           kc + 1, m0, n0, K, tid);
            CP_COMMIT();
            CP_WAIT(1);
        } else {
            CP_WAIT(0);
        }
        __syncthreads();

        uint32_t abase = sb + buf * BUF_BYTES;
        uint32_t lbase = abase + 16384;
        uint32_t bbase = abase + 32768;
        uint32_t cbase = abase + 49152;

        #pragma unroll
        for (int q = 0; q < 4; q++) {
            uint32_t ah[4][4], al[4][4], bh[2][4], bl[2][4];
            #pragma unroll
            for (int mi = 0; mi < 4; mi++) {
                int r = aRow + mi * 16;
                uint32_t off = ((uint32_t)(r * 128 + q * 32 + aCol)) ^ ((uint32_t)(r & 7) << 4);
                LDSM_X4(ah[mi][0], ah[mi][1], ah[mi][2], ah[mi][3], abase + off);
                LDSM_X4(al[mi][0], al[mi][1], al[mi][2], al[mi][3], lbase + off);
            }
            #pragma unroll
            for (int gi = 0; gi < 2; gi++) {
                int r = bRow + gi * 16;
                uint32_t off = ((uint32_t)(r * 128 + q * 32 + bCol)) ^ ((uint32_t)(r & 7) << 4);
                LDSM_X4(bh[gi][0], bh[gi][1], bh[gi][2], bh[gi][3], bbase + off);
                LDSM_X4(bl[gi][0], bl[gi][1], bl[gi][2], bl[gi][3], cbase + off);
            }
            #pragma unroll
            for (int mi = 0; mi < 4; mi++) {
                #pragma unroll
                for (int nj = 0; nj < 4; nj++) {
                    uint32_t bfh[2] = { bh[nj >> 1][(nj & 1) * 2], bh[nj >> 1][(nj & 1) * 2 + 1] };
                    uint32_t bfl[2] = { bl[nj >> 1][(nj & 1) * 2], bl[nj >> 1][(nj & 1) * 2 + 1] };
                    MMA_BF16(acc[mi][nj], ah[mi], bfh);   // Ah*Bh
                    MMA_BF16(acc[mi][nj], ah[mi], bfl);   // Ah*Bl
                    MMA_BF16(acc[mi][nj], al[mi], bfh);   // Al*Bh
                }
            }
        }
        __syncthreads();
        buf ^= 1;
    }

    float alpha = (mode == 1) ? g_alpha[g] : 0.f;

    #pragma unroll
    for (int mi = 0; mi < 4; mi++) {
        #pragma unroll
        for (int nj = 0; nj < 4; nj++) {
            int m = m0 + warpM * 64 + mi * 16 + (lane >> 2);
            int n = n0 + warpN * 32 + nj * 8 + (lane & 3) * 2;
            float c0 = acc[mi][nj][0], c1 = acc[mi][nj][1];
            float c2 = acc[mi][nj][2], c3 = acc[mi][nj][3];
            if (mode == 1) {
                float bx = bias[n], by = bias[n + 1];
                size_t coln = (size_t)g * HIDD + n;
                if (m < NN) {
                    float h0 = tanhf(alpha * (c0 + bx));
                    float h1 = tanhf(alpha * (c1 + by));
                    __nv_bfloat16 h0h, h0l, h1h, h1l;
                    split_bf16(h0, h0h, h0l); split_bf16(h1, h1h, h1l);
                    size_t base = (size_t)m * CONCAT + coln;
                    *(__nv_bfloat162*)(g_Hhi + base) = __halves2bfloat162(h0h, h1h);
                    *(__nv_bfloat162*)(g_Hlo + base) = __halves2bfloat162(h0l, h1l);
                }
                if (m + 8 < NN) {
                    float h2 = tanhf(alpha * (c2 + bx));
                    float h3 = tanhf(alpha * (c3 + by));
                    __nv_bfloat16 h2h, h2l, h3h, h3l;
                    split_bf16(h2, h2h, h2l); split_bf16(h3, h3h, h3l);
                    size_t base = (size_t)(m + 8) * CONCAT + coln;
                    *(__nv_bfloat162*)(g_Hhi + base) = __halves2bfloat162(h2h, h3h);
                    *(__nv_bfloat162*)(g_Hlo + base) = __halves2bfloat162(h2l, h3l);
                }
            } else {
                float bx = bias[n], by = bias[n + 1];
                if (m < NN)
                    *(float2*)(outp + (size_t)m * OUTD + n) = make_float2(c0 + bx, c1 + by);
                if (m + 8 < NN)
                    *(float2*)(outp + (size_t)(m + 8) * OUTD + n) = make_float2(c2 + bx, c3 + by);
            }
        }
    }
}

// ============================================================================
// Launch — inputs bound by element count (robust to metadata ordering)
// ============================================================================
extern "C" void kernel_launch(void* const* d_in, const int* in_sizes, int n_in,
                              void* d_out, int out_size) {
    const float* x = nullptr;
    const int*   e[GG]  = {nullptr, nullptr, nullptr};
    const float* W[GG]  = {nullptr, nullptr, nullptr};
    const float* b[GG]  = {nullptr, nullptr, nullptr};
    const float* alphas = nullptr;
    const float* W_lin  = nullptr;
    const float* b_lin  = nullptr;
    int ne = 0, nw = 0, nb = 0;

    for (int i = 0; i < n_in; i++) {
        int sz = in_sizes[i];
        if      (sz == NN * IND)      x = (const float*)d_in[i];
        else if (sz == 2 * EE)        { if (ne < GG) e[ne++] = (const int*)d_in[i]; }
        else if (sz == IND * HIDD)    { if (nw < GG) W[nw++] = (const float*)d_in[i]; }
        else if (sz == HIDD)          { if (nb < GG) b[nb++] = (const float*)d_in[i]; }
        else if (sz == GG)            alphas = (const float*)d_in[i];
        else if (sz == CONCAT * OUTD) W_lin = (const float*)d_in[i];
        else if (sz == OUTD)          b_lin = (const float*)d_in[i];
    }
    float* out = (float*)d_out;

    cudaFuncSetAttribute(mma_gemm_kernel, cudaFuncAttributeMaxDynamicSharedMemorySize,
                         GSMEM_TOTAL);

    zero_kernel<<<256, 256>>>(alphas);
    hist_kernel<<<(GG * EE + 255) / 256, 256>>>(e[0], e[1], e[2]);
    scan_kernel<<<GG, 1024>>>();
    fill_kernel<<<(GG * EE + 255) / 256, 256>>>(e[0], e[1], e[2]);
    conv_w_kernel<<<1024, 256>>>(W[0], W[1], W[2]);
    conv_wlin_kernel<<<512, 256>>>(W_lin);

    // Aggregation on X (L2-resident gather) -> AXhi/AXlo per graph
    dim3 gridA(NN, GG);
    agg_x_kernel<<<gridA, 128>>>(x);

    // GEMM1 per graph: [30000x512] @ W_g^T-layout, epilogue tanh -> Hhi/Hlo
    int mtiles = (NN + 127) / 128;   // 235
    dim3 grid1(HIDD / 128, mtiles);  // 4 x 235
    mma_gemm_kernel<<<grid1, 256, GSMEM_TOTAL>>>(nullptr, b[0], 1, IND, 0);
    mma_gemm_kernel<<<grid1, 256, GSMEM_TOTAL>>>(nullptr, b[1], 1, IND, 1);
    mma_gemm_kernel<<<grid1, 256, GSMEM_TOTAL>>>(nullptr, b[2], 1, IND, 2);

    // GEMM2: [30000x1536] @ BtL[256x1536]^T + b_lin -> out
    dim3 grid2(OUTD / 128, mtiles);  // 2 x 235
    mma_gemm_kernel<<<grid2, 256, GSMEM_TOTAL>>>(out, b_lin, 2, CONCAT, 0);
}

// round 6
// speedup vs baseline: 1.4318x; 1.4318x over previous
#include <cuda_runtime.h>
#include <cuda_fp16.h>
#include <math.h>
#include <stdint.h>

// Problem constants
#define NN 30000      // nodes
#define EE 150000     // edges per graph
#define IND 512
#define HIDD 512
#define OUTD 256
#define GG 3
#define CONCAT (HIDD * GG)   // 1536

// ============================================================================
// Scratch (device globals)
// ============================================================================
__device__ __half g_AXhi[(size_t)GG * NN * IND];  // aggregated, scaled X (fp16 hi)
__device__ __half g_AXlo[(size_t)GG * NN * IND];  // (fp16 lo residual)
__device__ __half g_Hhi[(size_t)NN * CONCAT];
__device__ __half g_Hlo[(size_t)NN * CONCAT];
__device__ __half g_Bt [(size_t)CONCAT * IND];    // [W0|W1|W2]^T : row n, col k (fp16)
__device__ __half g_BtL[(size_t)OUTD * CONCAT];   // W_lin^T : row n, col k (fp16)
__device__ int   g_deg_in [GG * NN];
__device__ int   g_deg_out[GG * NN];
__device__ int   g_off    [GG * (NN + 1)];
__device__ int   g_cursor [GG * NN];
__device__ int   g_csr_src[GG * EE];
__device__ float g_alpha  [GG];

// ============================================================================
// PTX helpers (plain-sm_103-legal: cp.async / ldmatrix / mma.sync)
// ============================================================================
__device__ __forceinline__ uint32_t smem_to_u32(const void* p) {
    uint32_t a;
    asm("{ .reg .u64 t; cvta.to.shared.u64 t, %1; cvt.u32.u64 %0, t; }" : "=r"(a) : "l"(p));
    return a;
}
#define CP16(dst32, src) \
    asm volatile("cp.async.cg.shared.global [%0], [%1], 16;" :: "r"(dst32), "l"(src))
#define CP_COMMIT() asm volatile("cp.async.commit_group;" ::: "memory")
#define CP_WAIT(n)  asm volatile("cp.async.wait_group %0;" :: "n"(n) : "memory")

#define LDSM_X4(r0, r1, r2, r3, addr) \
    asm volatile("ldmatrix.sync.aligned.m8n8.x4.shared.b16 {%0,%1,%2,%3}, [%4];" \
        : "=r"(r0), "=r"(r1), "=r"(r2), "=r"(r3) : "r"(addr))

#define MMA_F16(c, a, b) \
    asm volatile("mma.sync.aligned.m16n8k16.row.col.f32.f16.f16.f32 " \
        "{%0,%1,%2,%3}, {%4,%5,%6,%7}, {%8,%9}, {%0,%1,%2,%3};" \
        : "+f"((c)[0]), "+f"((c)[1]), "+f"((c)[2]), "+f"((c)[3]) \
        : "r"((a)[0]), "r"((a)[1]), "r"((a)[2]), "r"((a)[3]), "r"((b)[0]), "r"((b)[1]))

// ============================================================================
// Setup kernels
// ============================================================================
__global__ void zero_kernel(const float* __restrict__ alphas) {
    int i = blockIdx.x * blockDim.x + threadIdx.x;
    int total = 2 * GG * NN;
    for (int idx = i; idx < total; idx += gridDim.x * blockDim.x) {
        if (idx < GG * NN) g_deg_in[idx] = 0;
        else               g_deg_out[idx - GG * NN] = 0;
    }
    if (blockIdx.x == 0 && threadIdx.x == 0) {
        float m = alphas[0];
        for (int g = 1; g < GG; g++) m = fmaxf(m, alphas[g]);
        float s = 0.f, e[GG];
        for (int g = 0; g < GG; g++) { e[g] = expf(alphas[g] - m); s += e[g]; }
        for (int g = 0; g < GG; g++) g_alpha[g] = e[g] / s;
    }
}

__global__ void hist_kernel(const int* __restrict__ e0, const int* __restrict__ e1,
                            const int* __restrict__ e2) {
    int i = blockIdx.x * blockDim.x + threadIdx.x;
    if (i >= GG * EE) return;
    int g = i / EE, idx = i - g * EE;
    const int* e = (g == 0) ? e0 : (g == 1) ? e1 : e2;
    atomicAdd(&g_deg_out[g * NN + e[idx]], 1);
    atomicAdd(&g_deg_in [g * NN + e[EE + idx]], 1);
}

__global__ void scan_kernel() {
    int g = blockIdx.x;
    const int* cnt = g_deg_in + g * NN;
    int* off = g_off + g * (NN + 1);
    int* cur = g_cursor + g * NN;
    __shared__ int sh[1024];
    int carry = 0;
    for (int base = 0; base < NN; base += 1024) {
        int i = base + threadIdx.x;
        int v = (i < NN) ? cnt[i] : 0;
        sh[threadIdx.x] = v;
        __syncthreads();
        #pragma unroll
        for (int s = 1; s < 1024; s <<= 1) {
            int t = (threadIdx.x >= s) ? sh[threadIdx.x - s] : 0;
            __syncthreads();
            sh[threadIdx.x] += t;
            __syncthreads();
        }
        int incl = sh[threadIdx.x];
        if (i < NN) { off[i] = carry + incl - v; cur[i] = carry + incl - v; }
        carry += sh[1023];
        __syncthreads();
    }
    if (threadIdx.x == 0) off[NN] = carry;
}

__global__ void fill_kernel(const int* __restrict__ e0, const int* __restrict__ e1,
                            const int* __restrict__ e2) {
    int i = blockIdx.x * blockDim.x + threadIdx.x;
    if (i >= GG * EE) return;
    int g = i / EE, idx = i - g * EE;
    const int* e = (g == 0) ? e0 : (g == 1) ? e1 : e2;
    int src = e[idx];
    int dst = e[EE + idx];
    int p = atomicAdd(&g_cursor[g * NN + dst], 1);
    g_csr_src[g * EE + p] = src;
}

// ============================================================================
// fp32 -> fp16 hi/lo split
// ============================================================================
__device__ __forceinline__ void split_f16(float v, __half& hi, __half& lo) {
    hi = __float2half(v);
    lo = __float2half(v - __half2float(hi));
}

__global__ void conv_w_kernel(const float* __restrict__ W0, const float* __restrict__ W1,
                              const float* __restrict__ W2) {
    int i = blockIdx.x * blockDim.x + threadIdx.x;
    int total = GG * IND * HIDD;
    for (int idx = i; idx < total; idx += gridDim.x * blockDim.x) {
        int g = idx >> 18;
        int r = idx & 262143;
        int k = r >> 9;
        int n = r & 511;
        const float* W = (g == 0) ? W0 : (g == 1) ? W1 : W2;
        g_Bt[(size_t)(g * HIDD + n) * IND + k] = __float2half(W[k * HIDD + n]);
    }
}

__global__ void conv_wlin_kernel(const float* __restrict__ WL) {
    int i = blockIdx.x * blockDim.x + threadIdx.x;
    int total = CONCAT * OUTD;
    for (int idx = i; idx < total; idx += gridDim.x * blockDim.x) {
        int k = idx >> 8;
        int n = idx & 255;
        g_BtL[(size_t)n * CONCAT + k] = __float2half(WL[idx]);
    }
}

// ============================================================================
// Pre-GEMM aggregation on X:
// AX[g][dst] = rsqrt(deg_in[dst]) * sum_{e->dst} x[src]*rsqrt(deg_out[src])
// Output split into fp16 hi/lo (exact to 2^-22).
// ============================================================================
__global__ void __launch_bounds__(128)
agg_x_kernel(const float* __restrict__ x) {
    int dst = blockIdx.x;
    int g = blockIdx.y;
    int c = threadIdx.x * 4;

    int beg = g_off[g * (NN + 1) + dst];
    int end = g_off[g * (NN + 1) + dst + 1];
    const int* srcs = g_csr_src + g * EE;
    const int* dout = g_deg_out + g * NN;

    float4 acc = make_float4(0.f, 0.f, 0.f, 0.f);
    for (int e = beg; e < end; e++) {
        int s = srcs[e];
        int d = dout[s];
        float so = rsqrtf((float)(d > 1 ? d : 1));
        float4 v = *(const float4*)(x + (size_t)s * IND + c);
        acc.x += v.x * so; acc.y += v.y * so; acc.z += v.z * so; acc.w += v.w * so;
    }

    int di = g_deg_in[g * NN + dst];
    float rsv = rsqrtf((float)(di > 1 ? di : 1));
    acc.x *= rsv; acc.y *= rsv; acc.z *= rsv; acc.w *= rsv;

    size_t base = ((size_t)g * NN + dst) * IND + c;
    __half hi[4], lo[4];
    split_f16(acc.x, hi[0], lo[0]); split_f16(acc.y, hi[1], lo[1]);
    split_f16(acc.z, hi[2], lo[2]); split_f16(acc.w, hi[3], lo[3]);
    *(__half2*)(g_AXhi + base)     = __halves2half2(hi[0], hi[1]);
    *(__half2*)(g_AXhi + base + 2) = __halves2half2(hi[2], hi[3]);
    *(__half2*)(g_AXlo + base)     = __halves2half2(lo[0], lo[1]);
    *(__half2*)(g_AXlo + base + 2) = __halves2half2(lo[2], lo[3]);
}

// ============================================================================
// fp16 2-pass GEMM via mma.sync: D = (Ahi + Alo) @ Bhi  (= A @ f16(B))
// CTA tile 128x128, BK=64, 256 threads (8 warps 2x4, warp tile 64x32),
// cp.async double-buffered, swizzled ldmatrix, 2 CTAs/SM.
// mode 1 (per graph g): A=g_AX[g] (K=512), B=g_Bt[g],
//        epilogue tanh(alpha_g*(D+b_g)) -> Hhi/Hlo cols [g*512,(g+1)*512)
// mode 2: A=g_H (K=1536), B=g_BtL, C=outp (ldc=256), +bias
// SMEM per buffer (48KB): Ahi@0, Alo@16K, Bhi@32K; swizzle off^=(row&7)<<4
// ============================================================================
#define BUF_BYTES 49152
#define GSMEM_TOTAL (1024 + 2 * BUF_BYTES)

__device__ __forceinline__ void prefetch_chunk(uint32_t sdst,
        const __half* __restrict__ Ahi, const __half* __restrict__ Alo,
        const __half* __restrict__ B,
        int kc, int m0, int n0, int K, int tid) {
    int row = tid >> 1;
    int cb = (tid & 1) * 4;
    int mrow = m0 + row; if (mrow >= NN) mrow = NN - 1;   // clamped rows never stored
    int nrow = n0 + row;
    const char* pAh = (const char*)(Ahi + (size_t)mrow * K) + kc * 128;
    const char* pAl = (const char*)(Alo + (size_t)mrow * K) + kc * 128;
    const char* pB  = (const char*)(B   + (size_t)nrow * K) + kc * 128;
    #pragma unroll
    for (int q = 0; q < 4; q++) {
        int col = (cb + q) * 16;
        uint32_t swz = ((uint32_t)(row * 128 + col)) ^ ((uint32_t)(row & 7) << 4);
        CP16(sdst + swz,         pAh + col);
        CP16(sdst + 16384 + swz, pAl + col);
        CP16(sdst + 32768 + swz, pB  + col);
    }
}

__global__ void __launch_bounds__(256, 2)
mma_gemm_kernel(float* outp, const float* __restrict__ bias, int mode, int K, int g) {
    extern __shared__ char smem_raw[];
    uint32_t sb0 = smem_to_u32(smem_raw);
    uint32_t sb = (sb0 + 1023) & ~1023u;

    const __half *Ahi, *Alo, *B;
    if (mode == 1) {
        Ahi = g_AXhi + (size_t)g * NN * IND;  Alo = g_AXlo + (size_t)g * NN * IND;
        B   = g_Bt   + (size_t)g * HIDD * IND;
    } else {
        Ahi = g_Hhi; Alo = g_Hlo; B = g_BtL;
    }

    int tid = threadIdx.x;
    int lane = tid & 31, wid = tid >> 5;
    int warpM = wid >> 2, warpN = wid & 3;
    int n0 = blockIdx.x * 128;
    int m0 = blockIdx.y * 128;

    float acc[4][4][4];
    #pragma unroll
    for (int i = 0; i < 4; i++)
        #pragma unroll
        for (int j = 0; j < 4; j++)
            #pragma unroll
            for (int r = 0; r < 4; r++) acc[i][j][r] = 0.f;

    int aRow = warpM * 64 + (lane & 15);
    int aCol = (lane >> 4) * 16;
    int bRow = warpN * 32 + (lane & 7) + (lane >> 4) * 8;
    int bCol = ((lane >> 3) & 1) * 16;

    int nk = K >> 6;
    prefetch_chunk(sb, Ahi, Alo, B, 0, m0, n0, K, tid);
    CP_COMMIT();

    int buf = 0;
    for (int kc = 0; kc < nk; kc++) {
        if (kc + 1 < nk) {
            prefetch_chunk(sb + (buf ^ 1) * BUF_BYTES, Ahi, Alo, B, kc + 1, m0, n0, K, tid);
            CP_COMMIT();
            CP_WAIT(1);
        } else {
            CP_WAIT(0);
        }
        __syncthreads();

        uint32_t abase = sb + buf * BUF_BYTES;
        uint32_t lbase = abase + 16384;
        uint32_t bbase = abase + 32768;

        #pragma unroll
        for (int q = 0; q < 4; q++) {
            uint32_t bh[2][4];
            #pragma unroll
            for (int gi = 0; gi < 2; gi++) {
                int r = bRow + gi * 16;
                uint32_t off = ((uint32_t)(r * 128 + q * 32 + bCol)) ^ ((uint32_t)(r & 7) << 4);
                LDSM_X4(bh[gi][0], bh[gi][1], bh[gi][2], bh[gi][3], bbase + off);
            }
            #pragma unroll
            for (int mi = 0; mi < 4; mi++) {
                int r = aRow + mi * 16;
                uint32_t off = ((uint32_t)(r * 128 + q * 32 + aCol)) ^ ((uint32_t)(r & 7) << 4);
                uint32_t ah[4], al[4];
                LDSM_X4(ah[0], ah[1], ah[2], ah[3], abase + off);
                LDSM_X4(al[0], al[1], al[2], al[3], lbase + off);
                #pragma unroll
                for (int nj = 0; nj < 4; nj++) {
                    uint32_t bf[2] = { bh[nj >> 1][(nj & 1) * 2], bh[nj >> 1][(nj & 1) * 2 + 1] };
                    MMA_F16(acc[mi][nj], ah, bf);   // Ahi * B
                    MMA_F16(acc[mi][nj], al, bf);   // Alo * B
                }
            }
        }
        __syncthreads();
        buf ^= 1;
    }

    float alpha = (mode == 1) ? g_alpha[g] : 0.f;

    #pragma unroll
    for (int mi = 0; mi < 4; mi++) {
        #pragma unroll
        for (int nj = 0; nj < 4; nj++) {
            int m = m0 + warpM * 64 + mi * 16 + (lane >> 2);
            int n = n0 + warpN * 32 + nj * 8 + (lane & 3) * 2;
            float c0 = acc[mi][nj][0], c1 = acc[mi][nj][1];
            float c2 = acc[mi][nj][2], c3 = acc[mi][nj][3];
            float bx = bias[n], by = bias[n + 1];
            if (mode == 1) {
                size_t coln = (size_t)g * HIDD + n;
                if (m < NN) {
                    float h0 = tanhf(alpha * (c0 + bx));
                    float h1 = tanhf(alpha * (c1 + by));
                    __half h0h, h0l, h1h, h1l;
                    split_f16(h0, h0h, h0l); split_f16(h1, h1h, h1l);
                    size_t base = (size_t)m * CONCAT + coln;
                    *(__half2*)(g_Hhi + base) = __halves2half2(h0h, h1h);
                    *(__half2*)(g_Hlo + base) = __halves2half2(h0l, h1l);
                }
                if (m + 8 < NN) {
                    float h2 = tanhf(alpha * (c2 + bx));
                    float h3 = tanhf(alpha * (c3 + by));
                    __half h2h, h2l, h3h, h3l;
                    split_f16(h2, h2h, h2l); split_f16(h3, h3h, h3l);
                    size_t base = (size_t)(m + 8) * CONCAT + coln;
                    *(__half2*)(g_Hhi + base) = __halves2half2(h2h, h3h);
                    *(__half2*)(g_Hlo + base) = __halves2half2(h2l, h3l);
                }
            } else {
                if (m < NN)
                    *(float2*)(outp + (size_t)m * OUTD + n) = make_float2(c0 + bx, c1 + by);
                if (m + 8 < NN)
                    *(float2*)(outp + (size_t)(m + 8) * OUTD + n) = make_float2(c2 + bx, c3 + by);
            }
        }
    }
}

// ============================================================================
// Launch — inputs bound by element count (robust to metadata ordering)
// ============================================================================
extern "C" void kernel_launch(void* const* d_in, const int* in_sizes, int n_in,
                              void* d_out, int out_size) {
    const float* x = nullptr;
    const int*   e[GG]  = {nullptr, nullptr, nullptr};
    const float* W[GG]  = {nullptr, nullptr, nullptr};
    const float* b[GG]  = {nullptr, nullptr, nullptr};
    const float* alphas = nullptr;
    const float* W_lin  = nullptr;
    const float* b_lin  = nullptr;
    int ne = 0, nw = 0, nb = 0;

    for (int i = 0; i < n_in; i++) {
        int sz = in_sizes[i];
        if      (sz == NN * IND)      x = (const float*)d_in[i];
        else if (sz == 2 * EE)        { if (ne < GG) e[ne++] = (const int*)d_in[i]; }
        else if (sz == IND * HIDD)    { if (nw < GG) W[nw++] = (const float*)d_in[i]; }
        else if (sz == HIDD)          { if (nb < GG) b[nb++] = (const float*)d_in[i]; }
        else if (sz == GG)            alphas = (const float*)d_in[i];
        else if (sz == CONCAT * OUTD) W_lin = (const float*)d_in[i];
        else if (sz == OUTD)          b_lin = (const float*)d_in[i];
    }
    float* out = (float*)d_out;

    cudaFuncSetAttribute(mma_gemm_kernel, cudaFuncAttributeMaxDynamicSharedMemorySize,
                         GSMEM_TOTAL);

    zero_kernel<<<256, 256>>>(alphas);
    hist_kernel<<<(GG * EE + 255) / 256, 256>>>(e[0], e[1], e[2]);
    scan_kernel<<<GG, 1024>>>();
    fill_kernel<<<(GG * EE + 255) / 256, 256>>>(e[0], e[1], e[2]);
    conv_w_kernel<<<1024, 256>>>(W[0], W[1], W[2]);
    conv_wlin_kernel<<<512, 256>>>(W_lin);

    // Aggregation on X (L2-resident gather) -> AXhi/AXlo per graph
    dim3 gridA(NN, GG);
    agg_x_kernel<<<gridA, 128>>>(x);

    // GEMM1 per graph: [30000x512] @ W_g (fp16 2-pass), epilogue tanh -> Hhi/Hlo
    int mtiles = (NN + 127) / 128;   // 235
    dim3 grid1(HIDD / 128, mtiles);  // 4 x 235
    mma_gemm_kernel<<<grid1, 256, GSMEM_TOTAL>>>(nullptr, b[0], 1, IND, 0);
    mma_gemm_kernel<<<grid1, 256, GSMEM_TOTAL>>>(nullptr, b[1], 1, IND, 1);
    mma_gemm_kernel<<<grid1, 256, GSMEM_TOTAL>>>(nullptr, b[2], 1, IND, 2);

    // GEMM2: [30000x1536] @ W_lin (fp16 2-pass) + b_lin -> out
    dim3 grid2(OUTD / 128, mtiles);  // 2 x 235
    mma_gemm_kernel<<<grid2, 256, GSMEM_TOTAL>>>(out, b_lin, 2, CONCAT, 0);
}

// round 7
// speedup vs baseline: 2.1157x; 1.4777x over previous
#include <cuda_runtime.h>
#include <cuda_fp16.h>
#include <math.h>
#include <stdint.h>

// Problem constants
#define NN 30000      // nodes
#define EE 150000     // edges per graph
#define IND 512
#define HIDD 512
#define OUTD 256
#define GG 3
#define CONCAT (HIDD * GG)   // 1536

// ============================================================================
// Scratch (device globals)
// ============================================================================
__device__ __half g_AX[(size_t)GG * NN * IND];    // aggregated, scaled X (fp16)
__device__ __half g_H [(size_t)NN * CONCAT];      // tanh(...) (fp16)
__device__ __half g_Bt [(size_t)CONCAT * IND];    // [W0|W1|W2]^T : row n, col k (fp16)
__device__ __half g_BtL[(size_t)OUTD * CONCAT];   // W_lin^T : row n, col k (fp16)
__device__ int   g_deg_in [GG * NN];
__device__ int   g_deg_out[GG * NN];
__device__ int   g_off    [GG * (NN + 1)];
__device__ int   g_cursor [GG * NN];
__device__ int   g_csr_src[GG * EE];
__device__ float g_alpha  [GG];

// ============================================================================
// PTX helpers (plain-sm_103-legal: cp.async / ldmatrix / mma.sync)
// ============================================================================
__device__ __forceinline__ uint32_t smem_to_u32(const void* p) {
    uint32_t a;
    asm("{ .reg .u64 t; cvta.to.shared.u64 t, %1; cvt.u32.u64 %0, t; }" : "=r"(a) : "l"(p));
    return a;
}
#define CP16(dst32, src) \
    asm volatile("cp.async.cg.shared.global [%0], [%1], 16;" :: "r"(dst32), "l"(src))
#define CP_COMMIT() asm volatile("cp.async.commit_group;" ::: "memory")
#define CP_WAIT(n)  asm volatile("cp.async.wait_group %0;" :: "n"(n) : "memory")

#define LDSM_X4(r0, r1, r2, r3, addr) \
    asm volatile("ldmatrix.sync.aligned.m8n8.x4.shared.b16 {%0,%1,%2,%3}, [%4];" \
        : "=r"(r0), "=r"(r1), "=r"(r2), "=r"(r3) : "r"(addr))

#define MMA_F16(c, a, b) \
    asm volatile("mma.sync.aligned.m16n8k16.row.col.f32.f16.f16.f32 " \
        "{%0,%1,%2,%3}, {%4,%5,%6,%7}, {%8,%9}, {%0,%1,%2,%3};" \
        : "+f"((c)[0]), "+f"((c)[1]), "+f"((c)[2]), "+f"((c)[3]) \
        : "r"((a)[0]), "r"((a)[1]), "r"((a)[2]), "r"((a)[3]), "r"((b)[0]), "r"((b)[1]))

// ============================================================================
// Setup kernels
// ============================================================================
__global__ void zero_kernel(const float* __restrict__ alphas) {
    int i = blockIdx.x * blockDim.x + threadIdx.x;
    int total = 2 * GG * NN;
    for (int idx = i; idx < total; idx += gridDim.x * blockDim.x) {
        if (idx < GG * NN) g_deg_in[idx] = 0;
        else               g_deg_out[idx - GG * NN] = 0;
    }
    if (blockIdx.x == 0 && threadIdx.x == 0) {
        float m = alphas[0];
        for (int g = 1; g < GG; g++) m = fmaxf(m, alphas[g]);
        float s = 0.f, e[GG];
        for (int g = 0; g < GG; g++) { e[g] = expf(alphas[g] - m); s += e[g]; }
        for (int g = 0; g < GG; g++) g_alpha[g] = e[g] / s;
    }
}

__global__ void hist_kernel(const int* __restrict__ e0, const int* __restrict__ e1,
                            const int* __restrict__ e2) {
    int i = blockIdx.x * blockDim.x + threadIdx.x;
    if (i >= GG * EE) return;
    int g = i / EE, idx = i - g * EE;
    const int* e = (g == 0) ? e0 : (g == 1) ? e1 : e2;
    atomicAdd(&g_deg_out[g * NN + e[idx]], 1);
    atomicAdd(&g_deg_in [g * NN + e[EE + idx]], 1);
}

__global__ void scan_kernel() {
    int g = blockIdx.x;
    const int* cnt = g_deg_in + g * NN;
    int* off = g_off + g * (NN + 1);
    int* cur = g_cursor + g * NN;
    __shared__ int sh[1024];
    int carry = 0;
    for (int base = 0; base < NN; base += 1024) {
        int i = base + threadIdx.x;
        int v = (i < NN) ? cnt[i] : 0;
        sh[threadIdx.x] = v;
        __syncthreads();
        #pragma unroll
        for (int s = 1; s < 1024; s <<= 1) {
            int t = (threadIdx.x >= s) ? sh[threadIdx.x - s] : 0;
            __syncthreads();
            sh[threadIdx.x] += t;
            __syncthreads();
        }
        int incl = sh[threadIdx.x];
        if (i < NN) { off[i] = carry + incl - v; cur[i] = carry + incl - v; }
        carry += sh[1023];
        __syncthreads();
    }
    if (threadIdx.x == 0) off[NN] = carry;
}

__global__ void fill_kernel(const int* __restrict__ e0, const int* __restrict__ e1,
                            const int* __restrict__ e2) {
    int i = blockIdx.x * blockDim.x + threadIdx.x;
    if (i >= GG * EE) return;
    int g = i / EE, idx = i - g * EE;
    const int* e = (g == 0) ? e0 : (g == 1) ? e1 : e2;
    int src = e[idx];
    int dst = e[EE + idx];
    int p = atomicAdd(&g_cursor[g * NN + dst], 1);
    g_csr_src[g * EE + p] = src;
}

// ============================================================================
// Weight conversions (fp32 -> fp16, transposed to [n][k])
// ============================================================================
__global__ void conv_w_kernel(const float* __restrict__ W0, const float* __restrict__ W1,
                              const float* __restrict__ W2) {
    int i = blockIdx.x * blockDim.x + threadIdx.x;
    int total = GG * IND * HIDD;
    for (int idx = i; idx < total; idx += gridDim.x * blockDim.x) {
        int g = idx >> 18;
        int r = idx & 262143;
        int k = r >> 9;
        int n = r & 511;
        const float* W = (g == 0) ? W0 : (g == 1) ? W1 : W2;
        g_Bt[(size_t)(g * HIDD + n) * IND + k] = __float2half(W[k * HIDD + n]);
    }
}

__global__ void conv_wlin_kernel(const float* __restrict__ WL) {
    int i = blockIdx.x * blockDim.x + threadIdx.x;
    int total = CONCAT * OUTD;
    for (int idx = i; idx < total; idx += gridDim.x * blockDim.x) {
        int k = idx >> 8;
        int n = idx & 255;
        g_BtL[(size_t)n * CONCAT + k] = __float2half(WL[idx]);
    }
}

// ============================================================================
// Pre-GEMM aggregation on X:
// AX[g][dst] = rsqrt(deg_in[dst]) * sum_{e->dst} x[src]*rsqrt(deg_out[src])
// fp32 accumulation, fp16 output.
// ============================================================================
__global__ void __launch_bounds__(128)
agg_x_kernel(const float* __restrict__ x) {
    int dst = blockIdx.x;
    int g = blockIdx.y;
    int c = threadIdx.x * 4;

    int beg = g_off[g * (NN + 1) + dst];
    int end = g_off[g * (NN + 1) + dst + 1];
    const int* srcs = g_csr_src + g * EE;
    const int* dout = g_deg_out + g * NN;

    float4 acc = make_float4(0.f, 0.f, 0.f, 0.f);
    for (int e = beg; e < end; e++) {
        int s = srcs[e];
        int d = dout[s];
        float so = rsqrtf((float)(d > 1 ? d : 1));
        float4 v = *(const float4*)(x + (size_t)s * IND + c);
        acc.x += v.x * so; acc.y += v.y * so; acc.z += v.z * so; acc.w += v.w * so;
    }

    int di = g_deg_in[g * NN + dst];
    float rsv = rsqrtf((float)(di > 1 ? di : 1));

    size_t base = ((size_t)g * NN + dst) * IND + c;
    *(__half2*)(g_AX + base)     = __halves2half2(__float2half(acc.x * rsv),
                                                  __float2half(acc.y * rsv));
    *(__half2*)(g_AX + base + 2) = __halves2half2(__float2half(acc.z * rsv),
                                                  __float2half(acc.w * rsv));
}

// ============================================================================
// Single-pass fp16 GEMM via mma.sync: D = f16(A) @ f16(B), fp32 accum.
// CTA tile 128x128, BK=64, 256 threads (8 warps 2x4, warp tile 64x32),
// cp.async double-buffered, swizzled ldmatrix, 2 CTAs/SM.
// mode 1 (per graph g): A=g_AX[g] (K=512), B=g_Bt[g],
//        epilogue tanh(alpha_g*(D+b_g)) -> g_H cols [g*512,(g+1)*512)
// mode 2: A=g_H (K=1536), B=g_BtL, C=outp (ldc=256), +bias
// SMEM per buffer (32KB): A@0, B@16K; swizzle off^=(row&7)<<4
// ============================================================================
#define BUF_BYTES 32768
#define GSMEM_TOTAL (1024 + 2 * BUF_BYTES)

__device__ __forceinline__ void prefetch_chunk(uint32_t sdst,
        const __half* __restrict__ A, const __half* __restrict__ B,
        int kc, int m0, int n0, int K, int tid) {
    int row = tid >> 1;
    int cb = (tid & 1) * 4;
    int mrow = m0 + row; if (mrow >= NN) mrow = NN - 1;   // clamped rows never stored
    int nrow = n0 + row;
    const char* pA = (const char*)(A + (size_t)mrow * K) + kc * 128;
    const char* pB = (const char*)(B + (size_t)nrow * K) + kc * 128;
    #pragma unroll
    for (int q = 0; q < 4; q++) {
        int col = (cb + q) * 16;
        uint32_t swz = ((uint32_t)(row * 128 + col)) ^ ((uint32_t)(row & 7) << 4);
        CP16(sdst + swz,         pA + col);
        CP16(sdst + 16384 + swz, pB + col);
    }
}

__global__ void __launch_bounds__(256, 2)
mma_gemm_kernel(float* outp, const float* __restrict__ bias, int mode, int K, int g) {
    extern __shared__ char smem_raw[];
    uint32_t sb0 = smem_to_u32(smem_raw);
    uint32_t sb = (sb0 + 1023) & ~1023u;

    const __half *A, *B;
    if (mode == 1) {
        A = g_AX + (size_t)g * NN * IND;
        B = g_Bt + (size_t)g * HIDD * IND;
    } else {
        A = g_H; B = g_BtL;
    }

    int tid = threadIdx.x;
    int lane = tid & 31, wid = tid >> 5;
    int warpM = wid >> 2, warpN = wid & 3;
    int n0 = blockIdx.x * 128;
    int m0 = blockIdx.y * 128;

    float acc[4][4][4];
    #pragma unroll
    for (int i = 0; i < 4; i++)
        #pragma unroll
        for (int j = 0; j < 4; j++)
            #pragma unroll
            for (int r = 0; r < 4; r++) acc[i][j][r] = 0.f;

    int aRow = warpM * 64 + (lane & 15);
    int aCol = (lane >> 4) * 16;
    int bRow = warpN * 32 + (lane & 7) + (lane >> 4) * 8;
    int bCol = ((lane >> 3) & 1) * 16;

    int nk = K >> 6;
    prefetch_chunk(sb, A, B, 0, m0, n0, K, tid);
    CP_COMMIT();

    int buf = 0;
    for (int kc = 0; kc < nk; kc++) {
        if (kc + 1 < nk) {
            prefetch_chunk(sb + (buf ^ 1) * BUF_BYTES, A, B, kc + 1, m0, n0, K, tid);
            CP_COMMIT();
            CP_WAIT(1);
        } else {
            CP_WAIT(0);
        }
        __syncthreads();

        uint32_t abase = sb + buf * BUF_BYTES;
        uint32_t bbase = abase + 16384;

        #pragma unroll
        for (int q = 0; q < 4; q++) {
            uint32_t bh[2][4];
            #pragma unroll
            for (int gi = 0; gi < 2; gi++) {
                int r = bRow + gi * 16;
                uint32_t off = ((uint32_t)(r * 128 + q * 32 + bCol)) ^ ((uint32_t)(r & 7) << 4);
                LDSM_X4(bh[gi][0], bh[gi][1], bh[gi][2], bh[gi][3], bbase + off);
            }
            #pragma unroll
            for (int mi = 0; mi < 4; mi++) {
                int r = aRow + mi * 16;
                uint32_t off = ((uint32_t)(r * 128 + q * 32 + aCol)) ^ ((uint32_t)(r & 7) << 4);
                uint32_t ah[4];
                LDSM_X4(ah[0], ah[1], ah[2], ah[3], abase + off);
                #pragma unroll
                for (int nj = 0; nj < 4; nj++) {
                    uint32_t bf[2] = { bh[nj >> 1][(nj & 1) * 2], bh[nj >> 1][(nj & 1) * 2 + 1] };
                    MMA_F16(acc[mi][nj], ah, bf);
                }
            }
        }
        __syncthreads();
        buf ^= 1;
    }

    float alpha = (mode == 1) ? g_alpha[g] : 0.f;

    #pragma unroll
    for (int mi = 0; mi < 4; mi++) {
        #pragma unroll
        for (int nj = 0; nj < 4; nj++) {
            int m = m0 + warpM * 64 + mi * 16 + (lane >> 2);
            int n = n0 + warpN * 32 + nj * 8 + (lane & 3) * 2;
            float c0 = acc[mi][nj][0], c1 = acc[mi][nj][1];
            float c2 = acc[mi][nj][2], c3 = acc[mi][nj][3];
            float bx = bias[n], by = bias[n + 1];
            if (mode == 1) {
                size_t coln = (size_t)g * HIDD + n;
                if (m < NN) {
                    float h0 = tanhf(alpha * (c0 + bx));
                    float h1 = tanhf(alpha * (c1 + by));
                    *(__half2*)(g_H + (size_t)m * CONCAT + coln) =
                        __halves2half2(__float2half(h0), __float2half(h1));
                }
                if (m + 8 < NN) {
                    float h2 = tanhf(alpha * (c2 + bx));
                    float h3 = tanhf(alpha * (c3 + by));
                    *(__half2*)(g_H + (size_t)(m + 8) * CONCAT + coln) =
                        __halves2half2(__float2half(h2), __float2half(h3));
                }
            } else {
                if (m < NN)
                    *(float2*)(outp + (size_t)m * OUTD + n) = make_float2(c0 + bx, c1 + by);
                if (m + 8 < NN)
                    *(float2*)(outp + (size_t)(m + 8) * OUTD + n) = make_float2(c2 + bx, c3 + by);
            }
        }
    }
}

// ============================================================================
// Launch — inputs bound by element count (robust to metadata ordering)
// ============================================================================
extern "C" void kernel_launch(void* const* d_in, const int* in_sizes, int n_in,
                              void* d_out, int out_size) {
    const float* x = nullptr;
    const int*   e[GG]  = {nullptr, nullptr, nullptr};
    const float* W[GG]  = {nullptr, nullptr, nullptr};
    const float* b[GG]  = {nullptr, nullptr, nullptr};
    const float* alphas = nullptr;
    const float* W_lin  = nullptr;
    const float* b_lin  = nullptr;
    int ne = 0, nw = 0, nb = 0;

    for (int i = 0; i < n_in; i++) {
        int sz = in_sizes[i];
        if      (sz == NN * IND)      x = (const float*)d_in[i];
        else if (sz == 2 * EE)        { if (ne < GG) e[ne++] = (const int*)d_in[i]; }
        else if (sz == IND * HIDD)    { if (nw < GG) W[nw++] = (const float*)d_in[i]; }
        else if (sz == HIDD)          { if (nb < GG) b[nb++] = (const float*)d_in[i]; }
        else if (sz == GG)            alphas = (const float*)d_in[i];
        else if (sz == CONCAT * OUTD) W_lin = (const float*)d_in[i];
        else if (sz == OUTD)          b_lin = (const float*)d_in[i];
    }
    float* out = (float*)d_out;

    cudaFuncSetAttribute(mma_gemm_kernel, cudaFuncAttributeMaxDynamicSharedMemorySize,
                         GSMEM_TOTAL);

    zero_kernel<<<256, 256>>>(alphas);
    hist_kernel<<<(GG * EE + 255) / 256, 256>>>(e[0], e[1], e[2]);
    scan_kernel<<<GG, 1024>>>();
    fill_kernel<<<(GG * EE + 255) / 256, 256>>>(e[0], e[1], e[2]);
    conv_w_kernel<<<1024, 256>>>(W[0], W[1], W[2]);
    conv_wlin_kernel<<<512, 256>>>(W_lin);

    // Aggregation on X (L2-resident gather) -> AX per graph (fp16)
    dim3 gridA(NN, GG);
    agg_x_kernel<<<gridA, 128>>>(x);

    // GEMM1 per graph: [30000x512] @ W_g (fp16 1-pass), epilogue tanh -> g_H
    int mtiles = (NN + 127) / 128;   // 235
    dim3 grid1(HIDD / 128, mtiles);  // 4 x 235
    mma_gemm_kernel<<<grid1, 256, GSMEM_TOTAL>>>(nullptr, b[0], 1, IND, 0);
    mma_gemm_kernel<<<grid1, 256, GSMEM_TOTAL>>>(nullptr, b[1], 1, IND, 1);
    mma_gemm_kernel<<<grid1, 256, GSMEM_TOTAL>>>(nullptr, b[2], 1, IND, 2);

    // GEMM2: [30000x1536] @ W_lin (fp16 1-pass) + b_lin -> out
    dim3 grid2(OUTD / 128, mtiles);  // 2 x 235
    mma_gemm_kernel<<<grid2, 256, GSMEM_TOTAL>>>(out, b_lin, 2, CONCAT, 0);
}

// round 8
// speedup vs baseline: 2.1397x; 1.0113x over previous
#include <cuda_runtime.h>
#include <cuda_fp16.h>
#include <math.h>
#include <stdint.h>

// Problem constants
#define NN 30000      // nodes
#define EE 150000     // edges per graph
#define IND 512
#define HIDD 512
#define OUTD 256
#define GG 3
#define CONCAT (HIDD * GG)   // 1536

// ============================================================================
// Scratch (device globals)
// ============================================================================
__device__ __half g_X16[(size_t)NN * IND];        // x in fp16
__device__ __half g_AX[(size_t)GG * NN * IND];    // aggregated, scaled X (fp16)
__device__ __half g_H [(size_t)NN * CONCAT];      // tanh(...) (fp16)
__device__ __half g_Bt [(size_t)CONCAT * IND];    // [W0|W1|W2]^T : row n, col k (fp16)
__device__ __half g_BtL[(size_t)OUTD * CONCAT];   // W_lin^T : row n, col k (fp16)
__device__ int   g_deg[2 * GG * NN];              // [0,GG*NN)=deg_in, [GG*NN,..)=deg_out
__device__ int   g_off    [GG * (NN + 1)];
__device__ int   g_cursor [GG * NN];
__device__ int   g_csr_src[GG * EE];
__device__ float g_alpha  [GG];

#define DEG_IN(g, i)  g_deg[(g) * NN + (i)]
#define DEG_OUT(g, i) g_deg[GG * NN + (g) * NN + (i)]

// ============================================================================
// PTX helpers (plain-sm_103-legal: cp.async / ldmatrix / mma.sync)
// ============================================================================
__device__ __forceinline__ uint32_t smem_to_u32(const void* p) {
    uint32_t a;
    asm("{ .reg .u64 t; cvta.to.shared.u64 t, %1; cvt.u32.u64 %0, t; }" : "=r"(a) : "l"(p));
    return a;
}
#define CP16(dst32, src) \
    asm volatile("cp.async.cg.shared.global [%0], [%1], 16;" :: "r"(dst32), "l"(src))
#define CP_COMMIT() asm volatile("cp.async.commit_group;" ::: "memory")
#define CP_WAIT(n)  asm volatile("cp.async.wait_group %0;" :: "n"(n) : "memory")

#define LDSM_X4(r0, r1, r2, r3, addr) \
    asm volatile("ldmatrix.sync.aligned.m8n8.x4.shared.b16 {%0,%1,%2,%3}, [%4];" \
        : "=r"(r0), "=r"(r1), "=r"(r2), "=r"(r3) : "r"(addr))

#define MMA_F16(c, a, b) \
    asm volatile("mma.sync.aligned.m16n8k16.row.col.f32.f16.f16.f32 " \
        "{%0,%1,%2,%3}, {%4,%5,%6,%7}, {%8,%9}, {%0,%1,%2,%3};" \
        : "+f"((c)[0]), "+f"((c)[1]), "+f"((c)[2]), "+f"((c)[3]) \
        : "r"((a)[0]), "r"((a)[1]), "r"((a)[2]), "r"((a)[3]), "r"((b)[0]), "r"((b)[1]))

// ============================================================================
// Setup kernels
// ============================================================================
__global__ void hist_kernel(const int* __restrict__ e0, const int* __restrict__ e1,
                            const int* __restrict__ e2) {
    int i = blockIdx.x * blockDim.x + threadIdx.x;
    if (i >= GG * EE) return;
    int g = i / EE, idx = i - g * EE;
    const int* e = (g == 0) ? e0 : (g == 1) ? e1 : e2;
    atomicAdd(&DEG_OUT(g, e[idx]), 1);
    atomicAdd(&DEG_IN (g, e[EE + idx]), 1);
}

// Per-graph exclusive scan of deg_in; block 0 thread 0 also computes softmax(alphas)
__global__ void scan_kernel(const float* __restrict__ alphas) {
    int g = blockIdx.x;
    if (g == 0 && threadIdx.x == 0) {
        float m = alphas[0];
        for (int i = 1; i < GG; i++) m = fmaxf(m, alphas[i]);
        float s = 0.f, e[GG];
        for (int i = 0; i < GG; i++) { e[i] = expf(alphas[i] - m); s += e[i]; }
        for (int i = 0; i < GG; i++) g_alpha[i] = e[i] / s;
    }
    const int* cnt = &DEG_IN(g, 0);
    int* off = g_off + g * (NN + 1);
    int* cur = g_cursor + g * NN;
    __shared__ int sh[1024];
    int carry = 0;
    for (int base = 0; base < NN; base += 1024) {
        int i = base + threadIdx.x;
        int v = (i < NN) ? cnt[i] : 0;
        sh[threadIdx.x] = v;
        __syncthreads();
        #pragma unroll
        for (int s = 1; s < 1024; s <<= 1) {
            int t = (threadIdx.x >= s) ? sh[threadIdx.x - s] : 0;
            __syncthreads();
            sh[threadIdx.x] += t;
            __syncthreads();
        }
        int incl = sh[threadIdx.x];
        if (i < NN) { off[i] = carry + incl - v; cur[i] = carry + incl - v; }
        carry += sh[1023];
        __syncthreads();
    }
    if (threadIdx.x == 0) off[NN] = carry;
}

__global__ void fill_kernel(const int* __restrict__ e0, const int* __restrict__ e1,
                            const int* __restrict__ e2) {
    int i = blockIdx.x * blockDim.x + threadIdx.x;
    if (i >= GG * EE) return;
    int g = i / EE, idx = i - g * EE;
    const int* e = (g == 0) ? e0 : (g == 1) ? e1 : e2;
    int src = e[idx];
    int dst = e[EE + idx];
    int p = atomicAdd(&g_cursor[g * NN + dst], 1);
    g_csr_src[g * EE + p] = src;
}

// ============================================================================
// Merged conversion: x -> fp16, W_g -> Bt (transposed), W_lin -> BtL (transposed)
// ============================================================================
#define CX_TOTAL   (NN * IND)                 // 15360000
#define CW_TOTAL   (GG * IND * HIDD)          // 786432
#define CWL_TOTAL  (CONCAT * OUTD)            // 393216
#define CONV_TOTAL (CX_TOTAL + CW_TOTAL + CWL_TOTAL)

__global__ void conv_all_kernel(const float* __restrict__ x,
                                const float* __restrict__ W0,
                                const float* __restrict__ W1,
                                const float* __restrict__ W2,
                                const float* __restrict__ WL) {
    int i = blockIdx.x * blockDim.x + threadIdx.x;
    for (int idx = i; idx < CONV_TOTAL; idx += gridDim.x * blockDim.x) {
        if (idx < CX_TOTAL) {
            g_X16[idx] = __float2half(x[idx]);
        } else if (idx < CX_TOTAL + CW_TOTAL) {
            int t = idx - CX_TOTAL;
            int g = t >> 18;
            int r = t & 262143;
            int k = r >> 9;
            int n = r & 511;
            const float* W = (g == 0) ? W0 : (g == 1) ? W1 : W2;
            g_Bt[(size_t)(g * HIDD + n) * IND + k] = __float2half(W[k * HIDD + n]);
        } else {
            int t = idx - CX_TOTAL - CW_TOTAL;
            int k = t >> 8;
            int n = t & 255;
            g_BtL[(size_t)n * CONCAT + k] = __float2half(WL[t]);
        }
    }
}

// ============================================================================
// Pre-GEMM aggregation on fp16 X:
// AX[g][dst] = rsqrt(deg_in[dst]) * sum_{e->dst} x16[src]*rsqrt(deg_out[src])
// fp32 accumulation, fp16 output. grid = (NN, GG), 128 threads, 4 halfs/thread.
// ============================================================================
__global__ void __launch_bounds__(128)
agg_x_kernel() {
    int dst = blockIdx.x;
    int g = blockIdx.y;
    int c = threadIdx.x * 4;

    int beg = g_off[g * (NN + 1) + dst];
    int end = g_off[g * (NN + 1) + dst + 1];
    const int* srcs = g_csr_src + g * EE;
    const int* dout = &DEG_OUT(g, 0);

    float4 acc = make_float4(0.f, 0.f, 0.f, 0.f);
    for (int e = beg; e < end; e++) {
        int s = srcs[e];
        int d = dout[s];
        float so = rsqrtf((float)(d > 1 ? d : 1));
        const __half2* xr = (const __half2*)(g_X16 + (size_t)s * IND + c);
        __half2 v01 = xr[0], v23 = xr[1];
        float2 f01 = __half22float2(v01), f23 = __half22float2(v23);
        acc.x += f01.x * so; acc.y += f01.y * so;
        acc.z += f23.x * so; acc.w += f23.y * so;
    }

    int di = DEG_IN(g, dst);
    float rsv = rsqrtf((float)(di > 1 ? di : 1));

    size_t base = ((size_t)g * NN + dst) * IND + c;
    *(__half2*)(g_AX + base)     = __halves2half2(__float2half(acc.x * rsv),
                                                  __float2half(acc.y * rsv));
    *(__half2*)(g_AX + base + 2) = __halves2half2(__float2half(acc.z * rsv),
                                                  __float2half(acc.w * rsv));
}

// ============================================================================
// Single-pass fp16 GEMM via mma.sync: D = f16(A) @ f16(B), fp32 accum.
// CTA tile 128x128, BK=64, 256 threads (8 warps 2x4, warp tile 64x32),
// cp.async double-buffered, swizzled ldmatrix, 2 CTAs/SM.
// mode 1: g = blockIdx.z; A=g_AX[g] (K=512), B=g_Bt[g],
//        epilogue tanh(alpha_g*(D+b_g)) -> g_H cols [g*512,(g+1)*512)
// mode 2: A=g_H (K=1536), B=g_BtL, C=outp (ldc=256), +bias0
// ============================================================================
#define BUF_BYTES 32768
#define GSMEM_TOTAL (1024 + 2 * BUF_BYTES)

__device__ __forceinline__ void prefetch_chunk(uint32_t sdst,
        const __half* __restrict__ A, const __half* __restrict__ B,
        int kc, int m0, int n0, int K, int tid) {
    int row = tid >> 1;
    int cb = (tid & 1) * 4;
    int mrow = m0 + row; if (mrow >= NN) mrow = NN - 1;   // clamped rows never stored
    int nrow = n0 + row;
    const char* pA = (const char*)(A + (size_t)mrow * K) + kc * 128;
    const char* pB = (const char*)(B + (size_t)nrow * K) + kc * 128;
    #pragma unroll
    for (int q = 0; q < 4; q++) {
        int col = (cb + q) * 16;
        uint32_t swz = ((uint32_t)(row * 128 + col)) ^ ((uint32_t)(row & 7) << 4);
        CP16(sdst + swz,         pA + col);
        CP16(sdst + 16384 + swz, pB + col);
    }
}

__global__ void __launch_bounds__(256, 2)
mma_gemm_kernel(float* outp, const float* __restrict__ bias0,
                const float* __restrict__ bias1, const float* __restrict__ bias2,
                int mode, int K) {
    extern __shared__ char smem_raw[];
    uint32_t sb0 = smem_to_u32(smem_raw);
    uint32_t sb = (sb0 + 1023) & ~1023u;

    int g = blockIdx.z;
    const __half *A, *B;
    const float* bias;
    if (mode == 1) {
        A = g_AX + (size_t)g * NN * IND;
        B = g_Bt + (size_t)g * HIDD * IND;
        bias = (g == 0) ? bias0 : (g == 1) ? bias1 : bias2;
    } else {
        A = g_H; B = g_BtL; bias = bias0;
    }

    int tid = threadIdx.x;
    int lane = tid & 31, wid = tid >> 5;
    int warpM = wid >> 2, warpN = wid & 3;
    int n0 = blockIdx.x * 128;
    int m0 = blockIdx.y * 128;

    float acc[4][4][4];
    #pragma unroll
    for (int i = 0; i < 4; i++)
        #pragma unroll
        for (int j = 0; j < 4; j++)
            #pragma unroll
            for (int r = 0; r < 4; r++) acc[i][j][r] = 0.f;

    int aRow = warpM * 64 + (lane & 15);
    int aCol = (lane >> 4) * 16;
    int bRow = warpN * 32 + (lane & 7) + (lane >> 4) * 8;
    int bCol = ((lane >> 3) & 1) * 16;

    int nk = K >> 6;
    prefetch_chunk(sb, A, B, 0, m0, n0, K, tid);
    CP_COMMIT();

    int buf = 0;
    for (int kc = 0; kc < nk; kc++) {
        if (kc + 1 < nk) {
            prefetch_chunk(sb + (buf ^ 1) * BUF_BYTES, A, B, kc + 1, m0, n0, K, tid);
            CP_COMMIT();
            CP_WAIT(1);
        } else {
            CP_WAIT(0);
        }
        __syncthreads();

        uint32_t abase = sb + buf * BUF_BYTES;
        uint32_t bbase = abase + 16384;

        #pragma unroll
        for (int q = 0; q < 4; q++) {
            uint32_t bh[2][4];
            #pragma unroll
            for (int gi = 0; gi < 2; gi++) {
                int r = bRow + gi * 16;
                uint32_t off = ((uint32_t)(r * 128 + q * 32 + bCol)) ^ ((uint32_t)(r & 7) << 4);
                LDSM_X4(bh[gi][0], bh[gi][1], bh[gi][2], bh[gi][3], bbase + off);
            }
            #pragma unroll
            for (int mi = 0; mi < 4; mi++) {
                int r = aRow + mi * 16;
                uint32_t off = ((uint32_t)(r * 128 + q * 32 + aCol)) ^ ((uint32_t)(r & 7) << 4);
                uint32_t ah[4];
                LDSM_X4(ah[0], ah[1], ah[2], ah[3], abase + off);
                #pragma unroll
                for (int nj = 0; nj < 4; nj++) {
                    uint32_t bf[2] = { bh[nj >> 1][(nj & 1) * 2], bh[nj >> 1][(nj & 1) * 2 + 1] };
                    MMA_F16(acc[mi][nj], ah, bf);
                }
            }
        }
        __syncthreads();
        buf ^= 1;
    }

    float alpha = (mode == 1) ? g_alpha[g] : 0.f;

    #pragma unroll
    for (int mi = 0; mi < 4; mi++) {
        #pragma unroll
        for (int nj = 0; nj < 4; nj++) {
            int m = m0 + warpM * 64 + mi * 16 + (lane >> 2);
            int n = n0 + warpN * 32 + nj * 8 + (lane & 3) * 2;
            float c0 = acc[mi][nj][0], c1 = acc[mi][nj][1];
            float c2 = acc[mi][nj][2], c3 = acc[mi][nj][3];
            float bx = bias[n], by = bias[n + 1];
            if (mode == 1) {
                size_t coln = (size_t)g * HIDD + n;
                if (m < NN) {
                    float h0 = tanhf(alpha * (c0 + bx));
                    float h1 = tanhf(alpha * (c1 + by));
                    *(__half2*)(g_H + (size_t)m * CONCAT + coln) =
                        __halves2half2(__float2half(h0), __float2half(h1));
                }
                if (m + 8 < NN) {
                    float h2 = tanhf(alpha * (c2 + bx));
                    float h3 = tanhf(alpha * (c3 + by));
                    *(__half2*)(g_H + (size_t)(m + 8) * CONCAT + coln) =
                        __halves2half2(__float2half(h2), __float2half(h3));
                }
            } else {
                if (m < NN)
                    *(float2*)(outp + (size_t)m * OUTD + n) = make_float2(c0 + bx, c1 + by);
                if (m + 8 < NN)
                    *(float2*)(outp + (size_t)(m + 8) * OUTD + n) = make_float2(c2 + bx, c3 + by);
            }
        }
    }
}

// ============================================================================
// Launch — inputs bound by element count (robust to metadata ordering)
// ============================================================================
extern "C" void kernel_launch(void* const* d_in, const int* in_sizes, int n_in,
                              void* d_out, int out_size) {
    const float* x = nullptr;
    const int*   e[GG]  = {nullptr, nullptr, nullptr};
    const float* W[GG]  = {nullptr, nullptr, nullptr};
    const float* b[GG]  = {nullptr, nullptr, nullptr};
    const float* alphas = nullptr;
    const float* W_lin  = nullptr;
    const float* b_lin  = nullptr;
    int ne = 0, nw = 0, nb = 0;

    for (int i = 0; i < n_in; i++) {
        int sz = in_sizes[i];
        if      (sz == NN * IND)      x = (const float*)d_in[i];
        else if (sz == 2 * EE)        { if (ne < GG) e[ne++] = (const int*)d_in[i]; }
        else if (sz == IND * HIDD)    { if (nw < GG) W[nw++] = (const float*)d_in[i]; }
        else if (sz == HIDD)          { if (nb < GG) b[nb++] = (const float*)d_in[i]; }
        else if (sz == GG)            alphas = (const float*)d_in[i];
        else if (sz == CONCAT * OUTD) W_lin = (const float*)d_in[i];
        else if (sz == OUTD)          b_lin = (const float*)d_in[i];
    }
    float* out = (float*)d_out;

    cudaFuncSetAttribute(mma_gemm_kernel, cudaFuncAttributeMaxDynamicSharedMemorySize,
                         GSMEM_TOTAL);

    // Zero degree arrays via memset node (not a kernel launch)
    void* degp = nullptr;
    cudaGetSymbolAddress(&degp, g_deg);
    cudaMemsetAsync(degp, 0, sizeof(int) * 2 * GG * NN, 0);

    // Kernel launches (ncu -s 5 -c 1 captures launch #6 = GEMM1)
    hist_kernel<<<(GG * EE + 255) / 256, 256>>>(e[0], e[1], e[2]);       // 1
    scan_kernel<<<GG, 1024>>>(alphas);                                    // 2
    fill_kernel<<<(GG * EE + 255) / 256, 256>>>(e[0], e[1], e[2]);       // 3
    conv_all_kernel<<<2048, 256>>>(x, W[0], W[1], W[2], W_lin);          // 4

    dim3 gridA(NN, GG);
    agg_x_kernel<<<gridA, 128>>>();                                       // 5

    int mtiles = (NN + 127) / 128;    // 235
    dim3 grid1(HIDD / 128, mtiles, GG);  // 4 x 235 x 3 (all branches, one launch)
    mma_gemm_kernel<<<grid1, 256, GSMEM_TOTAL>>>(nullptr, b[0], b[1], b[2], 1, IND);  // 6

    dim3 grid2(OUTD / 128, mtiles, 1);   // 2 x 235
    mma_gemm_kernel<<<grid2, 256, GSMEM_TOTAL>>>(out, b_lin, nullptr, nullptr, 2, CONCAT); // 7
}

// round 9
// speedup vs baseline: 2.1756x; 1.0168x over previous
#include <cuda_runtime.h>
#include <cuda_fp16.h>
#include <math.h>
#include <stdint.h>

// Problem constants
#define NN 30000      // nodes
#define EE 150000     // edges per graph
#define IND 512
#define HIDD 512
#define OUTD 256
#define GG 3
#define CONCAT (HIDD * GG)   // 1536

// ============================================================================
// Scratch (device globals)
// ============================================================================
__device__ __half g_X16[(size_t)NN * IND];        // x in fp16
__device__ __half g_AX[(size_t)GG * NN * IND];    // aggregated, scaled X (fp16)
__device__ __half g_H [(size_t)NN * CONCAT];      // tanh(...) (fp16)
__device__ __half g_Bt [(size_t)CONCAT * IND];    // [W0|W1|W2]^T : row n, col k (fp16)
__device__ __half g_BtL[(size_t)OUTD * CONCAT];   // W_lin^T : row n, col k (fp16)
__device__ int   g_deg[2 * GG * NN];              // [0,GG*NN)=deg_in, rest deg_out
__device__ int   g_off    [GG * (NN + 1)];
__device__ int   g_cursor [GG * NN];
__device__ int   g_csr_src[GG * EE];
__device__ float g_alpha  [GG];

#define DEG_IN(g, i)  g_deg[(g) * NN + (i)]
#define DEG_OUT(g, i) g_deg[GG * NN + (g) * NN + (i)]

// ============================================================================
// PTX helpers (plain-sm_103-legal: cp.async / ldmatrix / mma.sync)
// ============================================================================
__device__ __forceinline__ uint32_t smem_to_u32(const void* p) {
    uint32_t a;
    asm("{ .reg .u64 t; cvta.to.shared.u64 t, %1; cvt.u32.u64 %0, t; }" : "=r"(a) : "l"(p));
    return a;
}
#define CP16(dst32, src) \
    asm volatile("cp.async.cg.shared.global [%0], [%1], 16;" :: "r"(dst32), "l"(src))
#define CP_COMMIT() asm volatile("cp.async.commit_group;" ::: "memory")
#define CP_WAIT(n)  asm volatile("cp.async.wait_group %0;" :: "n"(n) : "memory")

#define LDSM_X4(r0, r1, r2, r3, addr) \
    asm volatile("ldmatrix.sync.aligned.m8n8.x4.shared.b16 {%0,%1,%2,%3}, [%4];" \
        : "=r"(r0), "=r"(r1), "=r"(r2), "=r"(r3) : "r"(addr))

#define MMA_F16(c, a, b) \
    asm volatile("mma.sync.aligned.m16n8k16.row.col.f32.f16.f16.f32 " \
        "{%0,%1,%2,%3}, {%4,%5,%6,%7}, {%8,%9}, {%0,%1,%2,%3};" \
        : "+f"((c)[0]), "+f"((c)[1]), "+f"((c)[2]), "+f"((c)[3]) \
        : "r"((a)[0]), "r"((a)[1]), "r"((a)[2]), "r"((a)[3]), "r"((b)[0]), "r"((b)[1]))

// ============================================================================
// Setup kernels
// ============================================================================
__global__ void hist_kernel(const int* __restrict__ e0, const int* __restrict__ e1,
                            const int* __restrict__ e2) {
    int i = blockIdx.x * blockDim.x + threadIdx.x;
    if (i >= GG * EE) return;
    int g = i / EE, idx = i - g * EE;
    const int* e = (g == 0) ? e0 : (g == 1) ? e1 : e2;
    atomicAdd(&DEG_OUT(g, e[idx]), 1);
    atomicAdd(&DEG_IN (g, e[EE + idx]), 1);
}

// Work-efficient per-graph scan: 30 serial elems/thread + one block scan.
// Block 0 thread 0 also computes softmax(alphas).
#define SCHUNK 30   // 1024*30 = 30720 >= NN
__global__ void scan_kernel(const float* __restrict__ alphas) {
    int g = blockIdx.x;
    if (g == 0 && threadIdx.x == 0) {
        float m = alphas[0];
        for (int i = 1; i < GG; i++) m = fmaxf(m, alphas[i]);
        float s = 0.f, e[GG];
        for (int i = 0; i < GG; i++) { e[i] = expf(alphas[i] - m); s += e[i]; }
        for (int i = 0; i < GG; i++) g_alpha[i] = e[i] / s;
    }
    const int* cnt = &DEG_IN(g, 0);
    int* off = g_off + g * (NN + 1);
    int* cur = g_cursor + g * NN;
    __shared__ int sh[1024];
    int t = threadIdx.x;
    int base = t * SCHUNK;

    int s = 0;
    #pragma unroll 5
    for (int j = 0; j < SCHUNK; j++) {
        int i = base + j;
        s += (i < NN) ? cnt[i] : 0;
    }
    sh[t] = s;
    __syncthreads();
    #pragma unroll
    for (int st = 1; st < 1024; st <<= 1) {
        int v = (t >= st) ? sh[t - st] : 0;
        __syncthreads();
        sh[t] += v;
        __syncthreads();
    }
    int run = sh[t] - s;   // exclusive prefix of this thread's chunk
    #pragma unroll 5
    for (int j = 0; j < SCHUNK; j++) {
        int i = base + j;
        if (i < NN) {
            off[i] = run; cur[i] = run;
            run += cnt[i];
        }
    }
    if (t == 1023) off[NN] = sh[1023];
}

__global__ void fill_kernel(const int* __restrict__ e0, const int* __restrict__ e1,
                            const int* __restrict__ e2) {
    int i = blockIdx.x * blockDim.x + threadIdx.x;
    if (i >= GG * EE) return;
    int g = i / EE, idx = i - g * EE;
    const int* e = (g == 0) ? e0 : (g == 1) ? e1 : e2;
    int src = e[idx];
    int dst = e[EE + idx];
    int p = atomicAdd(&g_cursor[g * NN + dst], 1);
    g_csr_src[g * EE + p] = src;
}

// ============================================================================
// Merged conversion (vectorized): x -> fp16 (float4 loads, half2 stores);
// W transposes with coalesced WRITES (strided reads ride L2, W is tiny).
// ============================================================================
#define CX4_TOTAL  (NN * IND / 4)             // 3,840,000 float4
#define CW_TOTAL   (GG * IND * HIDD)          // 786,432
#define CWL_TOTAL  (CONCAT * OUTD)            // 393,216
#define CONV_TOTAL (CX4_TOTAL + CW_TOTAL + CWL_TOTAL)

__global__ void conv_all_kernel(const float* __restrict__ x,
                                const float* __restrict__ W0,
                                const float* __restrict__ W1,
                                const float* __restrict__ W2,
                                const float* __restrict__ WL) {
    int i = blockIdx.x * blockDim.x + threadIdx.x;
    const float4* x4 = (const float4*)x;
    __half2* X2 = (__half2*)g_X16;
    for (int idx = i; idx < CONV_TOTAL; idx += gridDim.x * blockDim.x) {
        if (idx < CX4_TOTAL) {
            float4 v = x4[idx];
            X2[idx * 2]     = __floats2half2_rn(v.x, v.y);
            X2[idx * 2 + 1] = __floats2half2_rn(v.z, v.w);
        } else if (idx < CX4_TOTAL + CW_TOTAL) {
            int t = idx - CX4_TOTAL;
            int k = t & 511;              // fastest -> coalesced write
            int n = (t >> 9) & 511;
            int g = t >> 18;
            const float* W = (g == 0) ? W0 : (g == 1) ? W1 : W2;
            g_Bt[(size_t)(g * HIDD + n) * IND + k] = __float2half(W[k * HIDD + n]);
        } else {
            int t = idx - CX4_TOTAL - CW_TOTAL;
            int k = t % CONCAT;           // fastest -> coalesced write
            int n = t / CONCAT;
            g_BtL[(size_t)n * CONCAT + k] = __float2half(WL[k * OUTD + n]);
        }
    }
}

// ============================================================================
// Pre-GEMM aggregation on fp16 X (fp32 accum, fp16 out)
// ============================================================================
__global__ void __launch_bounds__(128)
agg_x_kernel() {
    int dst = blockIdx.x;
    int g = blockIdx.y;
    int c = threadIdx.x * 4;

    int beg = g_off[g * (NN + 1) + dst];
    int end = g_off[g * (NN + 1) + dst + 1];
    const int* srcs = g_csr_src + g * EE;
    const int* dout = &DEG_OUT(g, 0);

    float4 acc = make_float4(0.f, 0.f, 0.f, 0.f);
    for (int e = beg; e < end; e++) {
        int s = srcs[e];
        int d = dout[s];
        float so = rsqrtf((float)(d > 1 ? d : 1));
        const __half2* xr = (const __half2*)(g_X16 + (size_t)s * IND + c);
        __half2 v01 = xr[0], v23 = xr[1];
        float2 f01 = __half22float2(v01), f23 = __half22float2(v23);
        acc.x += f01.x * so; acc.y += f01.y * so;
        acc.z += f23.x * so; acc.w += f23.y * so;
    }

    int di = DEG_IN(g, dst);
    float rsv = rsqrtf((float)(di > 1 ? di : 1));

    size_t base = ((size_t)g * NN + dst) * IND + c;
    *(__half2*)(g_AX + base)     = __halves2half2(__float2half(acc.x * rsv),
                                                  __float2half(acc.y * rsv));
    *(__half2*)(g_AX + base + 2) = __halves2half2(__float2half(acc.z * rsv),
                                                  __float2half(acc.w * rsv));
}

// ============================================================================
// Single-pass fp16 GEMM via mma.sync, 3-stage cp.async pipeline.
// CTA tile 128x128, BK=64, 256 threads (8 warps 2x4, warp tile 64x32),
// swizzled ldmatrix, 2 CTAs/SM, ONE barrier per chunk.
// mode 1: g=blockIdx.z; A=g_AX[g] (K=512), B=g_Bt[g]; tanh epilogue -> g_H
// mode 2: A=g_H (K=1536), B=g_BtL; +bias -> outp
// ============================================================================
#define BUF_BYTES 32768
#define NSTAGE 3
#define GSMEM_TOTAL (1024 + NSTAGE * BUF_BYTES)

__device__ __forceinline__ void prefetch_chunk(uint32_t sdst,
        const __half* __restrict__ A, const __half* __restrict__ B,
        int kc, int m0, int n0, int K, int tid) {
    int row = tid >> 1;
    int cb = (tid & 1) * 4;
    int mrow = m0 + row; if (mrow >= NN) mrow = NN - 1;   // clamped rows never stored
    int nrow = n0 + row;
    const char* pA = (const char*)(A + (size_t)mrow * K) + kc * 128;
    const char* pB = (const char*)(B + (size_t)nrow * K) + kc * 128;
    #pragma unroll
    for (int q = 0; q < 4; q++) {
        int col = (cb + q) * 16;
        uint32_t swz = ((uint32_t)(row * 128 + col)) ^ ((uint32_t)(row & 7) << 4);
        CP16(sdst + swz,         pA + col);
        CP16(sdst + 16384 + swz, pB + col);
    }
}

__global__ void __launch_bounds__(256, 2)
mma_gemm_kernel(float* outp, const float* __restrict__ bias0,
                const float* __restrict__ bias1, const float* __restrict__ bias2,
                int mode, int K) {
    extern __shared__ char smem_raw[];
    uint32_t sb0 = smem_to_u32(smem_raw);
    uint32_t sb = (sb0 + 1023) & ~1023u;

    int g = blockIdx.z;
    const __half *A, *B;
    const float* bias;
    if (mode == 1) {
        A = g_AX + (size_t)g * NN * IND;
        B = g_Bt + (size_t)g * HIDD * IND;
        bias = (g == 0) ? bias0 : (g == 1) ? bias1 : bias2;
    } else {
        A = g_H; B = g_BtL; bias = bias0;
    }

    int tid = threadIdx.x;
    int lane = tid & 31, wid = tid >> 5;
    int warpM = wid >> 2, warpN = wid & 3;
    int n0 = blockIdx.x * 128;
    int m0 = blockIdx.y * 128;

    float acc[4][4][4];
    #pragma unroll
    for (int i = 0; i < 4; i++)
        #pragma unroll
        for (int j = 0; j < 4; j++)
            #pragma unroll
            for (int r = 0; r < 4; r++) acc[i][j][r] = 0.f;

    int aRow = warpM * 64 + (lane & 15);
    int aCol = (lane >> 4) * 16;
    int bRow = warpN * 32 + (lane & 7) + (lane >> 4) * 8;
    int bCol = ((lane >> 3) & 1) * 16;

    int nk = K >> 6;
    // prologue: 2 chunks in flight
    prefetch_chunk(sb, A, B, 0, m0, n0, K, tid);
    CP_COMMIT();
    if (nk > 1) { prefetch_chunk(sb + BUF_BYTES, A, B, 1, m0, n0, K, tid); }
    CP_COMMIT();   // commit (possibly empty group keeps count consistent)

    for (int kc = 0; kc < nk; kc++) {
        if (kc + 2 < nk) CP_WAIT(1);
        else             CP_WAIT(0);
        __syncthreads();
        if (kc + 2 < nk) {
            prefetch_chunk(sb + ((kc + 2) % NSTAGE) * BUF_BYTES, A, B, kc + 2, m0, n0, K, tid);
            CP_COMMIT();
        }

        uint32_t abase = sb + (kc % NSTAGE) * BUF_BYTES;
        uint32_t bbase = abase + 16384;

        #pragma unroll
        for (int q = 0; q < 4; q++) {
            uint32_t bh[2][4];
            #pragma unroll
            for (int gi = 0; gi < 2; gi++) {
                int r = bRow + gi * 16;
                uint32_t off = ((uint32_t)(r * 128 + q * 32 + bCol)) ^ ((uint32_t)(r & 7) << 4);
                LDSM_X4(bh[gi][0], bh[gi][1], bh[gi][2], bh[gi][3], bbase + off);
            }
            #pragma unroll
            for (int mi = 0; mi < 4; mi++) {
                int r = aRow + mi * 16;
                uint32_t off = ((uint32_t)(r * 128 + q * 32 + aCol)) ^ ((uint32_t)(r & 7) << 4);
                uint32_t ah[4];
                LDSM_X4(ah[0], ah[1], ah[2], ah[3], abase + off);
                #pragma unroll
                for (int nj = 0; nj < 4; nj++) {
                    uint32_t bf[2] = { bh[nj >> 1][(nj & 1) * 2], bh[nj >> 1][(nj & 1) * 2 + 1] };
                    MMA_F16(acc[mi][nj], ah, bf);
                }
            }
        }
        __syncthreads();   // all reads of buf[kc%NSTAGE] done before its reuse at kc+NSTAGE
    }

    float alpha = (mode == 1) ? g_alpha[g] : 0.f;

    #pragma unroll
    for (int mi = 0; mi < 4; mi++) {
        #pragma unroll
        for (int nj = 0; nj < 4; nj++) {
            int m = m0 + warpM * 64 + mi * 16 + (lane >> 2);
            int n = n0 + warpN * 32 + nj * 8 + (lane & 3) * 2;
            float c0 = acc[mi][nj][0], c1 = acc[mi][nj][1];
            float c2 = acc[mi][nj][2], c3 = acc[mi][nj][3];
            float bx = bias[n], by = bias[n + 1];
            if (mode == 1) {
                size_t coln = (size_t)g * HIDD + n;
                if (m < NN) {
                    float h0 = tanhf(alpha * (c0 + bx));
                    float h1 = tanhf(alpha * (c1 + by));
                    *(__half2*)(g_H + (size_t)m * CONCAT + coln) =
                        __halves2half2(__float2half(h0), __float2half(h1));
                }
                if (m + 8 < NN) {
                    float h2 = tanhf(alpha * (c2 + bx));
                    float h3 = tanhf(alpha * (c3 + by));
                    *(__half2*)(g_H + (size_t)(m + 8) * CONCAT + coln) =
                        __halves2half2(__float2half(h2), __float2half(h3));
                }
            } else {
                if (m < NN)
                    *(float2*)(outp + (size_t)m * OUTD + n) = make_float2(c0 + bx, c1 + by);
                if (m + 8 < NN)
                    *(float2*)(outp + (size_t)(m + 8) * OUTD + n) = make_float2(c2 + bx, c3 + by);
            }
        }
    }
}

// ============================================================================
// Launch — inputs bound by element count; conv forked onto a second stream
// (capture-legal event fork/join) to overlap with hist/scan/fill.
// ============================================================================
extern "C" void kernel_launch(void* const* d_in, const int* in_sizes, int n_in,
                              void* d_out, int out_size) {
    const float* x = nullptr;
    const int*   e[GG]  = {nullptr, nullptr, nullptr};
    const float* W[GG]  = {nullptr, nullptr, nullptr};
    const float* b[GG]  = {nullptr, nullptr, nullptr};
    const float* alphas = nullptr;
    const float* W_lin  = nullptr;
    const float* b_lin  = nullptr;
    int ne = 0, nw = 0, nb = 0;

    for (int i = 0; i < n_in; i++) {
        int sz = in_sizes[i];
        if      (sz == NN * IND)      x = (const float*)d_in[i];
        else if (sz == 2 * EE)        { if (ne < GG) e[ne++] = (const int*)d_in[i]; }
        else if (sz == IND * HIDD)    { if (nw < GG) W[nw++] = (const float*)d_in[i]; }
        else if (sz == HIDD)          { if (nb < GG) b[nb++] = (const float*)d_in[i]; }
        else if (sz == GG)            alphas = (const float*)d_in[i];
        else if (sz == CONCAT * OUTD) W_lin = (const float*)d_in[i];
        else if (sz == OUTD)          b_lin = (const float*)d_in[i];
    }
    float* out = (float*)d_out;

    static cudaStream_t s2 = nullptr;
    static cudaEvent_t ev_fork = nullptr, ev_join = nullptr;
    if (!s2) {
        cudaStreamCreateWithFlags(&s2, cudaStreamNonBlocking);
        cudaEventCreateWithFlags(&ev_fork, cudaEventDisableTiming);
        cudaEventCreateWithFlags(&ev_join, cudaEventDisableTiming);
    }

    cudaFuncSetAttribute(mma_gemm_kernel, cudaFuncAttributeMaxDynamicSharedMemorySize,
                         GSMEM_TOTAL);

    void* degp = nullptr;
    cudaGetSymbolAddress(&degp, g_deg);
    cudaMemsetAsync(degp, 0, sizeof(int) * 2 * GG * NN, 0);

    // Fork: conv_all runs on s2, overlapped with hist/scan/fill on stream 0
    cudaEventRecord(ev_fork, 0);
    cudaStreamWaitEvent(s2, ev_fork, 0);
    conv_all_kernel<<<1184, 256, 0, s2>>>(x, W[0], W[1], W[2], W_lin);

    hist_kernel<<<(GG * EE + 255) / 256, 256>>>(e[0], e[1], e[2]);
    scan_kernel<<<GG, 1024>>>(alphas);
    fill_kernel<<<(GG * EE + 255) / 256, 256>>>(e[0], e[1], e[2]);

    // Join: agg needs X16 (s2) + CSR (stream 0)
    cudaEventRecord(ev_join, s2);
    cudaStreamWaitEvent(0, ev_join, 0);

    dim3 gridA(NN, GG);
    agg_x_kernel<<<gridA, 128>>>();

    int mtiles = (NN + 127) / 128;       // 235
    dim3 grid1(HIDD / 128, mtiles, GG);  // 4 x 235 x 3
    mma_gemm_kernel<<<grid1, 256, GSMEM_TOTAL>>>(nullptr, b[0], b[1], b[2], 1, IND);

    dim3 grid2(OUTD / 128, mtiles, 1);   // 2 x 235
    mma_gemm_kernel<<<grid2, 256, GSMEM_TOTAL>>>(out, b_lin, nullptr, nullptr, 2, CONCAT);
}

// round 10
// speedup vs baseline: 2.6705x; 1.2275x over previous
#include <cuda_runtime.h>
#include <cuda_fp16.h>
#include <math.h>
#include <stdint.h>

// Problem constants
#define NN 30000      // nodes
#define EE 150000     // edges per graph
#define IND 512
#define HIDD 512
#define OUTD 256
#define GG 3
#define CONCAT (HIDD * GG)   // 1536

// ============================================================================
// Scratch (device globals)
// ============================================================================
__device__ __half g_X16[(size_t)NN * IND];        // x in fp16
__device__ __half g_AX[(size_t)GG * NN * IND];    // aggregated, scaled X (fp16)
__device__ __half g_H [(size_t)NN * CONCAT];      // tanh(...) (fp16)
__device__ __half g_Bt [(size_t)CONCAT * IND];    // [W0|W1|W2]^T : row n, col k (fp16)
__device__ __half g_BtL[(size_t)OUTD * CONCAT];   // W_lin^T : row n, col k (fp16)
__device__ int   g_deg[2 * GG * NN];              // [0,GG*NN)=deg_in, rest deg_out
__device__ int   g_off    [GG * (NN + 1)];
__device__ int   g_cursor [GG * NN];
__device__ int   g_csr_src[GG * EE];
__device__ float g_alpha  [GG];

#define DEG_IN(g, i)  g_deg[(g) * NN + (i)]
#define DEG_OUT(g, i) g_deg[GG * NN + (g) * NN + (i)]

// ============================================================================
// PTX helpers (plain-sm_103-legal: cp.async / ldmatrix / mma.sync)
// ============================================================================
__device__ __forceinline__ uint32_t smem_to_u32(const void* p) {
    uint32_t a;
    asm("{ .reg .u64 t; cvta.to.shared.u64 t, %1; cvt.u32.u64 %0, t; }" : "=r"(a) : "l"(p));
    return a;
}
#define CP16(dst32, src) \
    asm volatile("cp.async.cg.shared.global [%0], [%1], 16;" :: "r"(dst32), "l"(src))
#define CP_COMMIT() asm volatile("cp.async.commit_group;" ::: "memory")
#define CP_WAIT(n)  asm volatile("cp.async.wait_group %0;" :: "n"(n) : "memory")

#define LDSM_X4(r0, r1, r2, r3, addr) \
    asm volatile("ldmatrix.sync.aligned.m8n8.x4.shared.b16 {%0,%1,%2,%3}, [%4];" \
        : "=r"(r0), "=r"(r1), "=r"(r2), "=r"(r3) : "r"(addr))

#define MMA_F16(c, a, b) \
    asm volatile("mma.sync.aligned.m16n8k16.row.col.f32.f16.f16.f32 " \
        "{%0,%1,%2,%3}, {%4,%5,%6,%7}, {%8,%9}, {%0,%1,%2,%3};" \
        : "+f"((c)[0]), "+f"((c)[1]), "+f"((c)[2]), "+f"((c)[3]) \
        : "r"((a)[0]), "r"((a)[1]), "r"((a)[2]), "r"((a)[3]), "r"((b)[0]), "r"((b)[1]))

// fast tanh: 1 - 2/(exp(2x)+1); rel err ~1e-6, ~6 instrs
__device__ __forceinline__ float fast_tanh(float x) {
    float e = __expf(2.0f * x);
    return 1.0f - __fdividef(2.0f, e + 1.0f);
}

// ============================================================================
// Setup kernels
// ============================================================================
__global__ void hist_kernel(const int* __restrict__ e0, const int* __restrict__ e1,
                            const int* __restrict__ e2) {
    int i = blockIdx.x * blockDim.x + threadIdx.x;
    if (i >= GG * EE) return;
    int g = i / EE, idx = i - g * EE;
    const int* e = (g == 0) ? e0 : (g == 1) ? e1 : e2;
    atomicAdd(&DEG_OUT(g, e[idx]), 1);
    atomicAdd(&DEG_IN (g, e[EE + idx]), 1);
}

// Work-efficient per-graph scan (30 serial elems/thread + one block scan);
// block 0 thread 0 computes softmax(alphas).
#define SCHUNK 30   // 1024*30 = 30720 >= NN
__global__ void scan_kernel(const float* __restrict__ alphas) {
    int g = blockIdx.x;
    if (g == 0 && threadIdx.x == 0) {
        float m = alphas[0];
        for (int i = 1; i < GG; i++) m = fmaxf(m, alphas[i]);
        float s = 0.f, e[GG];
        for (int i = 0; i < GG; i++) { e[i] = expf(alphas[i] - m); s += e[i]; }
        for (int i = 0; i < GG; i++) g_alpha[i] = e[i] / s;
    }
    const int* cnt = &DEG_IN(g, 0);
    int* off = g_off + g * (NN + 1);
    int* cur = g_cursor + g * NN;
    __shared__ int sh[1024];
    int t = threadIdx.x;
    int base = t * SCHUNK;

    int s = 0;
    #pragma unroll 5
    for (int j = 0; j < SCHUNK; j++) {
        int i = base + j;
        s += (i < NN) ? cnt[i] : 0;
    }
    sh[t] = s;
    __syncthreads();
    #pragma unroll
    for (int st = 1; st < 1024; st <<= 1) {
        int v = (t >= st) ? sh[t - st] : 0;
        __syncthreads();
        sh[t] += v;
        __syncthreads();
    }
    int run = sh[t] - s;
    #pragma unroll 5
    for (int j = 0; j < SCHUNK; j++) {
        int i = base + j;
        if (i < NN) {
            off[i] = run; cur[i] = run;
            run += cnt[i];
        }
    }
    if (t == 1023) off[NN] = sh[1023];
}

__global__ void fill_kernel(const int* __restrict__ e0, const int* __restrict__ e1,
                            const int* __restrict__ e2) {
    int i = blockIdx.x * blockDim.x + threadIdx.x;
    if (i >= GG * EE) return;
    int g = i / EE, idx = i - g * EE;
    const int* e = (g == 0) ? e0 : (g == 1) ? e1 : e2;
    int src = e[idx];
    int dst = e[EE + idx];
    int p = atomicAdd(&g_cursor[g * NN + dst], 1);
    g_csr_src[g * EE + p] = src;
}

// ============================================================================
// Merged conversion (vectorized)
// ============================================================================
#define CX4_TOTAL  (NN * IND / 4)
#define CW_TOTAL   (GG * IND * HIDD)
#define CWL_TOTAL  (CONCAT * OUTD)
#define CONV_TOTAL (CX4_TOTAL + CW_TOTAL + CWL_TOTAL)

__global__ void conv_all_kernel(const float* __restrict__ x,
                                const float* __restrict__ W0,
                                const float* __restrict__ W1,
                                const float* __restrict__ W2,
                                const float* __restrict__ WL) {
    int i = blockIdx.x * blockDim.x + threadIdx.x;
    const float4* x4 = (const float4*)x;
    __half2* X2 = (__half2*)g_X16;
    for (int idx = i; idx < CONV_TOTAL; idx += gridDim.x * blockDim.x) {
        if (idx < CX4_TOTAL) {
            float4 v = x4[idx];
            X2[idx * 2]     = __floats2half2_rn(v.x, v.y);
            X2[idx * 2 + 1] = __floats2half2_rn(v.z, v.w);
        } else if (idx < CX4_TOTAL + CW_TOTAL) {
            int t = idx - CX4_TOTAL;
            int k = t & 511;
            int n = (t >> 9) & 511;
            int g = t >> 18;
            const float* W = (g == 0) ? W0 : (g == 1) ? W1 : W2;
            g_Bt[(size_t)(g * HIDD + n) * IND + k] = __float2half(W[k * HIDD + n]);
        } else {
            int t = idx - CX4_TOTAL - CW_TOTAL;
            int k = t % CONCAT;
            int n = t / CONCAT;
            g_BtL[(size_t)n * CONCAT + k] = __float2half(WL[k * OUTD + n]);
        }
    }
}

// ============================================================================
// Pre-GEMM aggregation on fp16 X (fp32 accum, fp16 out)
// ============================================================================
__global__ void __launch_bounds__(128)
agg_x_kernel() {
    int dst = blockIdx.x;
    int g = blockIdx.y;
    int c = threadIdx.x * 4;

    int beg = g_off[g * (NN + 1) + dst];
    int end = g_off[g * (NN + 1) + dst + 1];
    const int* srcs = g_csr_src + g * EE;
    const int* dout = &DEG_OUT(g, 0);

    float4 acc = make_float4(0.f, 0.f, 0.f, 0.f);
    for (int e = beg; e < end; e++) {
        int s = srcs[e];
        int d = dout[s];
        float so = rsqrtf((float)(d > 1 ? d : 1));
        const __half2* xr = (const __half2*)(g_X16 + (size_t)s * IND + c);
        __half2 v01 = xr[0], v23 = xr[1];
        float2 f01 = __half22float2(v01), f23 = __half22float2(v23);
        acc.x += f01.x * so; acc.y += f01.y * so;
        acc.z += f23.x * so; acc.w += f23.y * so;
    }

    int di = DEG_IN(g, dst);
    float rsv = rsqrtf((float)(di > 1 ? di : 1));

    size_t base = ((size_t)g * NN + dst) * IND + c;
    *(__half2*)(g_AX + base)     = __halves2half2(__float2half(acc.x * rsv),
                                                  __float2half(acc.y * rsv));
    *(__half2*)(g_AX + base + 2) = __halves2half2(__float2half(acc.z * rsv),
                                                  __float2half(acc.w * rsv));
}

// ============================================================================
// Templated single-pass fp16 GEMM. BN=128 fixed; BM in {128, 64}.
// 256 threads = 8 warps (2 in M x 4 in N); warp tile (BM/2) x 32.
// 3-stage cp.async pipeline, ONE barrier per chunk, swizzled ldmatrix.
// mode 1: g=blockIdx.z; A=g_AX[g] (K=512), B=g_Bt[g]; tanh -> g_H
// mode 2: A=g_H (K=1536), B=g_BtL; +bias -> outp
// Stage bytes = (BM+128)*128 : A rows [0,BM), B rows at offset BM*128.
// ============================================================================
#define NSTAGE 3

template<int BM>
__device__ __forceinline__ void prefetch_chunk(uint32_t sdst,
        const __half* __restrict__ A, const __half* __restrict__ B,
        int kc, int m0, int n0, int K, int tid) {
    const int TOT = (BM + 128) * 8;   // 16B segments
    #pragma unroll
    for (int i = tid; i < TOT; i += 256) {
        int row = i >> 3;
        int col = (i & 7) * 16;
        if (row < BM) {
            int mrow = m0 + row; if (mrow >= NN) mrow = NN - 1;  // clamped rows never stored
            uint32_t swz = ((uint32_t)(row * 128 + col)) ^ ((uint32_t)(row & 7) << 4);
            CP16(sdst + swz, (const char*)(A + (size_t)mrow * K) + kc * 128 + col);
        } else {
            int r2 = row - BM;
            uint32_t swz = ((uint32_t)(r2 * 128 + col)) ^ ((uint32_t)(r2 & 7) << 4);
            CP16(sdst + BM * 128 + swz, (const char*)(B + (size_t)(n0 + r2) * K) + kc * 128 + col);
        }
    }
}

template<int BM, int MI>
__global__ void __launch_bounds__(256, 2)
mma_gemm_kernel(float* outp, const float* __restrict__ bias0,
                const float* __restrict__ bias1, const float* __restrict__ bias2,
                int mode, int K) {
    constexpr int SBYTES = (BM + 128) * 128;
    extern __shared__ char smem_raw[];
    uint32_t sb0 = smem_to_u32(smem_raw);
    uint32_t sb = (sb0 + 1023) & ~1023u;

    int g = blockIdx.z;
    const __half *A, *B;
    const float* bias;
    if (mode == 1) {
        A = g_AX + (size_t)g * NN * IND;
        B = g_Bt + (size_t)g * HIDD * IND;
        bias = (g == 0) ? bias0 : (g == 1) ? bias1 : bias2;
    } else {
        A = g_H; B = g_BtL; bias = bias0;
    }

    int tid = threadIdx.x;
    int lane = tid & 31, wid = tid >> 5;
    int warpM = wid >> 2, warpN = wid & 3;
    int n0 = blockIdx.x * 128;
    int m0 = blockIdx.y * BM;

    float acc[MI][4][4];
    #pragma unroll
    for (int i = 0; i < MI; i++)
        #pragma unroll
        for (int j = 0; j < 4; j++)
            #pragma unroll
            for (int r = 0; r < 4; r++) acc[i][j][r] = 0.f;

    int aRow = warpM * (BM / 2) + (lane & 15);
    int aCol = (lane >> 4) * 16;
    int bRow = warpN * 32 + (lane & 7) + (lane >> 4) * 8;
    int bCol = ((lane >> 3) & 1) * 16;

    int nk = K >> 6;
    prefetch_chunk<BM>(sb, A, B, 0, m0, n0, K, tid);
    CP_COMMIT();
    if (nk > 1) { prefetch_chunk<BM>(sb + SBYTES, A, B, 1, m0, n0, K, tid); }
    CP_COMMIT();

    for (int kc = 0; kc < nk; kc++) {
        if (kc + 2 < nk) CP_WAIT(1);
        else             CP_WAIT(0);
        __syncthreads();   // single barrier per chunk: orders data-ready AND buffer reuse
        if (kc + 2 < nk) {
            prefetch_chunk<BM>(sb + ((kc + 2) % NSTAGE) * SBYTES, A, B, kc + 2, m0, n0, K, tid);
            CP_COMMIT();
        }

        uint32_t abase = sb + (kc % NSTAGE) * SBYTES;
        uint32_t bbase = abase + BM * 128;

        #pragma unroll
        for (int q = 0; q < 4; q++) {
            uint32_t bh[2][4];
            #pragma unroll
            for (int gi = 0; gi < 2; gi++) {
                int r = bRow + gi * 16;
                uint32_t off = ((uint32_t)(r * 128 + q * 32 + bCol)) ^ ((uint32_t)(r & 7) << 4);
                LDSM_X4(bh[gi][0], bh[gi][1], bh[gi][2], bh[gi][3], bbase + off);
            }
            #pragma unroll
            for (int mi = 0; mi < MI; mi++) {
                int r = aRow + mi * 16;
                uint32_t off = ((uint32_t)(r * 128 + q * 32 + aCol)) ^ ((uint32_t)(r & 7) << 4);
                uint32_t ah[4];
                LDSM_X4(ah[0], ah[1], ah[2], ah[3], abase + off);
                #pragma unroll
                for (int nj = 0; nj < 4; nj++) {
                    uint32_t bf[2] = { bh[nj >> 1][(nj & 1) * 2], bh[nj >> 1][(nj & 1) * 2 + 1] };
                    MMA_F16(acc[mi][nj], ah, bf);
                }
            }
        }
    }

    float alpha = (mode == 1) ? g_alpha[g] : 0.f;

    #pragma unroll
    for (int mi = 0; mi < MI; mi++) {
        #pragma unroll
        for (int nj = 0; nj < 4; nj++) {
            int m = m0 + warpM * (BM / 2) + mi * 16 + (lane >> 2);
            int n = n0 + warpN * 32 + nj * 8 + (lane & 3) * 2;
            float c0 = acc[mi][nj][0], c1 = acc[mi][nj][1];
            float c2 = acc[mi][nj][2], c3 = acc[mi][nj][3];
            float bx = bias[n], by = bias[n + 1];
            if (mode == 1) {
                size_t coln = (size_t)g * HIDD + n;
                if (m < NN) {
                    float h0 = fast_tanh(alpha * (c0 + bx));
                    float h1 = fast_tanh(alpha * (c1 + by));
                    *(__half2*)(g_H + (size_t)m * CONCAT + coln) =
                        __halves2half2(__float2half(h0), __float2half(h1));
                }
                if (m + 8 < NN) {
                    float h2 = fast_tanh(alpha * (c2 + bx));
                    float h3 = fast_tanh(alpha * (c3 + by));
                    *(__half2*)(g_H + (size_t)(m + 8) * CONCAT + coln) =
                        __halves2half2(__float2half(h2), __float2half(h3));
                }
            } else {
                if (m < NN)
                    *(float2*)(outp + (size_t)m * OUTD + n) = make_float2(c0 + bx, c1 + by);
                if (m + 8 < NN)
                    *(float2*)(outp + (size_t)(m + 8) * OUTD + n) = make_float2(c2 + bx, c3 + by);
            }
        }
    }
}

#define SMEM1 (1024 + NSTAGE * (128 + 128) * 128)   // 99328
#define SMEM2 (1024 + NSTAGE * (64 + 128) * 128)    // 74752

// ============================================================================
// Launch
// ============================================================================
extern "C" void kernel_launch(void* const* d_in, const int* in_sizes, int n_in,
                              void* d_out, int out_size) {
    const float* x = nullptr;
    const int*   e[GG]  = {nullptr, nullptr, nullptr};
    const float* W[GG]  = {nullptr, nullptr, nullptr};
    const float* b[GG]  = {nullptr, nullptr, nullptr};
    const float* alphas = nullptr;
    const float* W_lin  = nullptr;
    const float* b_lin  = nullptr;
    int ne = 0, nw = 0, nb = 0;

    for (int i = 0; i < n_in; i++) {
        int sz = in_sizes[i];
        if      (sz == NN * IND)      x = (const float*)d_in[i];
        else if (sz == 2 * EE)        { if (ne < GG) e[ne++] = (const int*)d_in[i]; }
        else if (sz == IND * HIDD)    { if (nw < GG) W[nw++] = (const float*)d_in[i]; }
        else if (sz == HIDD)          { if (nb < GG) b[nb++] = (const float*)d_in[i]; }
        else if (sz == GG)            alphas = (const float*)d_in[i];
        else if (sz == CONCAT * OUTD) W_lin = (const float*)d_in[i];
        else if (sz == OUTD)          b_lin = (const float*)d_in[i];
    }
    float* out = (float*)d_out;

    static cudaStream_t s2 = nullptr;
    static cudaEvent_t ev_fork = nullptr, ev_join = nullptr;
    if (!s2) {
        cudaStreamCreateWithFlags(&s2, cudaStreamNonBlocking);
        cudaEventCreateWithFlags(&ev_fork, cudaEventDisableTiming);
        cudaEventCreateWithFlags(&ev_join, cudaEventDisableTiming);
    }

    cudaFuncSetAttribute((const void*)mma_gemm_kernel<128, 4>,
                         cudaFuncAttributeMaxDynamicSharedMemorySize, SMEM1);
    cudaFuncSetAttribute((const void*)mma_gemm_kernel<64, 2>,
                         cudaFuncAttributeMaxDynamicSharedMemorySize, SMEM2);

    void* degp = nullptr;
    cudaGetSymbolAddress(&degp, g_deg);
    cudaMemsetAsync(degp, 0, sizeof(int) * 2 * GG * NN, 0);

    // Fork conv onto s2 to overlap with CSR build
    cudaEventRecord(ev_fork, 0);
    cudaStreamWaitEvent(s2, ev_fork, 0);
    conv_all_kernel<<<1184, 256, 0, s2>>>(x, W[0], W[1], W[2], W_lin);

    hist_kernel<<<(GG * EE + 255) / 256, 256>>>(e[0], e[1], e[2]);
    scan_kernel<<<GG, 1024>>>(alphas);
    fill_kernel<<<(GG * EE + 255) / 256, 256>>>(e[0], e[1], e[2]);

    cudaEventRecord(ev_join, s2);
    cudaStreamWaitEvent(0, ev_join, 0);

    dim3 gridA(NN, GG);
    agg_x_kernel<<<gridA, 128>>>();

    // GEMM1: BM=128 tiles, all 3 branches in one launch
    int mtiles1 = (NN + 127) / 128;          // 235
    dim3 grid1(HIDD / 128, mtiles1, GG);     // 4 x 235 x 3
    mma_gemm_kernel<128, 4><<<grid1, 256, SMEM1>>>(nullptr, b[0], b[1], b[2], 1, IND);

    // GEMM2: BM=64 tiles (better wave packing: 938 CTAs)
    int mtiles2 = (NN + 63) / 64;            // 469
    dim3 grid2(OUTD / 128, mtiles2, 1);      // 2 x 469
    mma_gemm_kernel<64, 2><<<grid2, 256, SMEM2>>>(out, b_lin, nullptr, nullptr, 2, CONCAT);
}

// round 11
// speedup vs baseline: 2.7177x; 1.0177x over previous
#include <cuda_runtime.h>
#include <cuda_fp16.h>
#include <math.h>
#include <stdint.h>

// Problem constants
#define NN 30000      // nodes
#define EE 150000     // edges per graph
#define IND 512
#define HIDD 512
#define OUTD 256
#define GG 3
#define CONCAT (HIDD * GG)   // 1536

// ============================================================================
// Scratch (device globals)
// ============================================================================
__device__ __half g_X16[(size_t)NN * IND];        // x in fp16
__device__ __half g_AX[(size_t)GG * NN * IND];    // aggregated, scaled X (fp16)
__device__ __half g_H [(size_t)NN * CONCAT];      // tanh(...) (fp16)
__device__ __half g_Bt [(size_t)CONCAT * IND];    // [W0|W1|W2]^T : row n, col k (fp16)
__device__ __half g_BtL[(size_t)OUTD * CONCAT];   // W_lin^T : row n, col k (fp16)
__device__ int   g_deg[2 * GG * NN];              // [0,GG*NN)=deg_in, rest deg_out
__device__ int   g_off    [GG * (NN + 1)];
__device__ int   g_cursor [GG * NN];
__device__ int   g_csr_src[GG * EE];
__device__ float g_alpha  [GG];

#define DEG_IN(g, i)  g_deg[(g) * NN + (i)]
#define DEG_OUT(g, i) g_deg[GG * NN + (g) * NN + (i)]

// ============================================================================
// PTX helpers (plain-sm_103-legal: cp.async / ldmatrix / mma.sync)
// ============================================================================
__device__ __forceinline__ uint32_t smem_to_u32(const void* p) {
    uint32_t a;
    asm("{ .reg .u64 t; cvta.to.shared.u64 t, %1; cvt.u32.u64 %0, t; }" : "=r"(a) : "l"(p));
    return a;
}
#define CP16(dst32, src) \
    asm volatile("cp.async.cg.shared.global [%0], [%1], 16;" :: "r"(dst32), "l"(src))
#define CP_COMMIT() asm volatile("cp.async.commit_group;" ::: "memory")
#define CP_WAIT(n)  asm volatile("cp.async.wait_group %0;" :: "n"(n) : "memory")

#define LDSM_X4(r0, r1, r2, r3, addr) \
    asm volatile("ldmatrix.sync.aligned.m8n8.x4.shared.b16 {%0,%1,%2,%3}, [%4];" \
        : "=r"(r0), "=r"(r1), "=r"(r2), "=r"(r3) : "r"(addr))

#define MMA_F16(c, a, b) \
    asm volatile("mma.sync.aligned.m16n8k16.row.col.f32.f16.f16.f32 " \
        "{%0,%1,%2,%3}, {%4,%5,%6,%7}, {%8,%9}, {%0,%1,%2,%3};" \
        : "+f"((c)[0]), "+f"((c)[1]), "+f"((c)[2]), "+f"((c)[3]) \
        : "r"((a)[0]), "r"((a)[1]), "r"((a)[2]), "r"((a)[3]), "r"((b)[0]), "r"((b)[1]))

// fast tanh: 1 - 2/(exp(2x)+1); rel err ~1e-6
__device__ __forceinline__ float fast_tanh(float x) {
    float e = __expf(2.0f * x);
    return 1.0f - __fdividef(2.0f, e + 1.0f);
}

// ============================================================================
// Setup kernels
// ============================================================================
__global__ void hist_kernel(const int* __restrict__ e0, const int* __restrict__ e1,
                            const int* __restrict__ e2) {
    int i = blockIdx.x * blockDim.x + threadIdx.x;
    if (i >= GG * EE) return;
    int g = i / EE, idx = i - g * EE;
    const int* e = (g == 0) ? e0 : (g == 1) ? e1 : e2;
    atomicAdd(&DEG_OUT(g, e[idx]), 1);
    atomicAdd(&DEG_IN (g, e[EE + idx]), 1);
}

#define SCHUNK 30   // 1024*30 = 30720 >= NN
__global__ void scan_kernel(const float* __restrict__ alphas) {
    int g = blockIdx.x;
    if (g == 0 && threadIdx.x == 0) {
        float m = alphas[0];
        for (int i = 1; i < GG; i++) m = fmaxf(m, alphas[i]);
        float s = 0.f, e[GG];
        for (int i = 0; i < GG; i++) { e[i] = expf(alphas[i] - m); s += e[i]; }
        for (int i = 0; i < GG; i++) g_alpha[i] = e[i] / s;
    }
    const int* cnt = &DEG_IN(g, 0);
    int* off = g_off + g * (NN + 1);
    int* cur = g_cursor + g * NN;
    __shared__ int sh[1024];
    int t = threadIdx.x;
    int base = t * SCHUNK;

    int s = 0;
    #pragma unroll 5
    for (int j = 0; j < SCHUNK; j++) {
        int i = base + j;
        s += (i < NN) ? cnt[i] : 0;
    }
    sh[t] = s;
    __syncthreads();
    #pragma unroll
    for (int st = 1; st < 1024; st <<= 1) {
        int v = (t >= st) ? sh[t - st] : 0;
        __syncthreads();
        sh[t] += v;
        __syncthreads();
    }
    int run = sh[t] - s;
    #pragma unroll 5
    for (int j = 0; j < SCHUNK; j++) {
        int i = base + j;
        if (i < NN) {
            off[i] = run; cur[i] = run;
            run += cnt[i];
        }
    }
    if (t == 1023) off[NN] = sh[1023];
}

__global__ void fill_kernel(const int* __restrict__ e0, const int* __restrict__ e1,
                            const int* __restrict__ e2) {
    int i = blockIdx.x * blockDim.x + threadIdx.x;
    if (i >= GG * EE) return;
    int g = i / EE, idx = i - g * EE;
    const int* e = (g == 0) ? e0 : (g == 1) ? e1 : e2;
    int src = e[idx];
    int dst = e[EE + idx];
    int p = atomicAdd(&g_cursor[g * NN + dst], 1);
    g_csr_src[g * EE + p] = src;
}

// ============================================================================
// Merged conversion (vectorized)
// ============================================================================
#define CX4_TOTAL  (NN * IND / 4)
#define CW_TOTAL   (GG * IND * HIDD)
#define CWL_TOTAL  (CONCAT * OUTD)
#define CONV_TOTAL (CX4_TOTAL + CW_TOTAL + CWL_TOTAL)

__global__ void conv_all_kernel(const float* __restrict__ x,
                                const float* __restrict__ W0,
                                const float* __restrict__ W1,
                                const float* __restrict__ W2,
                                const float* __restrict__ WL) {
    int i = blockIdx.x * blockDim.x + threadIdx.x;
    const float4* x4 = (const float4*)x;
    __half2* X2 = (__half2*)g_X16;
    for (int idx = i; idx < CONV_TOTAL; idx += gridDim.x * blockDim.x) {
        if (idx < CX4_TOTAL) {
            float4 v = x4[idx];
            X2[idx * 2]     = __floats2half2_rn(v.x, v.y);
            X2[idx * 2 + 1] = __floats2half2_rn(v.z, v.w);
        } else if (idx < CX4_TOTAL + CW_TOTAL) {
            int t = idx - CX4_TOTAL;
            int k = t & 511;
            int n = (t >> 9) & 511;
            int g = t >> 18;
            const float* W = (g == 0) ? W0 : (g == 1) ? W1 : W2;
            g_Bt[(size_t)(g * HIDD + n) * IND + k] = __float2half(W[k * HIDD + n]);
        } else {
            int t = idx - CX4_TOTAL - CW_TOTAL;
            int k = t % CONCAT;
            int n = t / CONCAT;
            g_BtL[(size_t)n * CONCAT + k] = __float2half(WL[k * OUTD + n]);
        }
    }
}

// ============================================================================
// Pre-GEMM aggregation on fp16 X (fp32 accum, fp16 out)
// ============================================================================
__global__ void __launch_bounds__(128)
agg_x_kernel() {
    int dst = blockIdx.x;
    int g = blockIdx.y;
    int c = threadIdx.x * 4;

    int beg = g_off[g * (NN + 1) + dst];
    int end = g_off[g * (NN + 1) + dst + 1];
    const int* srcs = g_csr_src + g * EE;
    const int* dout = &DEG_OUT(g, 0);

    float4 acc = make_float4(0.f, 0.f, 0.f, 0.f);
    for (int e = beg; e < end; e++) {
        int s = srcs[e];
        int d = dout[s];
        float so = rsqrtf((float)(d > 1 ? d : 1));
        const __half2* xr = (const __half2*)(g_X16 + (size_t)s * IND + c);
        __half2 v01 = xr[0], v23 = xr[1];
        float2 f01 = __half22float2(v01), f23 = __half22float2(v23);
        acc.x += f01.x * so; acc.y += f01.y * so;
        acc.z += f23.x * so; acc.w += f23.y * so;
    }

    int di = DEG_IN(g, dst);
    float rsv = rsqrtf((float)(di > 1 ? di : 1));

    size_t base = ((size_t)g * NN + dst) * IND + c;
    *(__half2*)(g_AX + base)     = __halves2half2(__float2half(acc.x * rsv),
                                                  __float2half(acc.y * rsv));
    *(__half2*)(g_AX + base + 2) = __halves2half2(__float2half(acc.z * rsv),
                                                  __float2half(acc.w * rsv));
}

// ============================================================================
// Single-pass fp16 GEMM: 128 threads, 4 warps (2x2), warp tile (BM/2) x 64.
// CTA tile BM x 128, BK=64, 3-stage cp.async pipeline, 1 barrier/chunk,
// swizzled ldmatrix, 2 CTAs/SM. MMA:LDSM reuse = 4 (square warp tiles).
// mode 1: g=blockIdx.z; A=g_AX[g] (K=512), B=g_Bt[g]; tanh -> g_H
// mode 2: A=g_H (K=1536), B=g_BtL; +bias -> outp
// ============================================================================
#define NSTAGE 3

template<int BM>
__device__ __forceinline__ void prefetch_chunk(uint32_t sdst,
        const __half* __restrict__ A, const __half* __restrict__ B,
        int kc, int m0, int n0, int K, int tid) {
    const int TOT = (BM + 128) * 8;   // 16B segments
    #pragma unroll
    for (int i = tid; i < TOT; i += 128) {
        int row = i >> 3;
        int col = (i & 7) * 16;
        if (row < BM) {
            int mrow = m0 + row; if (mrow >= NN) mrow = NN - 1;  // clamped rows never stored
            uint32_t swz = ((uint32_t)(row * 128 + col)) ^ ((uint32_t)(row & 7) << 4);
            CP16(sdst + swz, (const char*)(A + (size_t)mrow * K) + kc * 128 + col);
        } else {
            int r2 = row - BM;
            uint32_t swz = ((uint32_t)(r2 * 128 + col)) ^ ((uint32_t)(r2 & 7) << 4);
            CP16(sdst + BM * 128 + swz, (const char*)(B + (size_t)(n0 + r2) * K) + kc * 128 + col);
        }
    }
}

template<int BM, int MI>
__global__ void __launch_bounds__(128, 2)
mma_gemm_kernel(float* outp, const float* __restrict__ bias0,
                const float* __restrict__ bias1, const float* __restrict__ bias2,
                int mode, int K) {
    constexpr int SBYTES = (BM + 128) * 128;
    extern __shared__ char smem_raw[];
    uint32_t sb0 = smem_to_u32(smem_raw);
    uint32_t sb = (sb0 + 1023) & ~1023u;

    int g = blockIdx.z;
    const __half *A, *B;
    const float* bias;
    if (mode == 1) {
        A = g_AX + (size_t)g * NN * IND;
        B = g_Bt + (size_t)g * HIDD * IND;
        bias = (g == 0) ? bias0 : (g == 1) ? bias1 : bias2;
    } else {
        A = g_H; B = g_BtL; bias = bias0;
    }

    int tid = threadIdx.x;
    int lane = tid & 31, wid = tid >> 5;
    int warpM = wid >> 1, warpN = wid & 1;     // 2x2 warp grid
    int n0 = blockIdx.x * 128;
    int m0 = blockIdx.y * BM;

    float acc[MI][8][4];
    #pragma unroll
    for (int i = 0; i < MI; i++)
        #pragma unroll
        for (int j = 0; j < 8; j++)
            #pragma unroll
            for (int r = 0; r < 4; r++) acc[i][j][r] = 0.f;

    int aRow = warpM * (BM / 2) + (lane & 15);
    int aCol = (lane >> 4) * 16;
    int bRow = warpN * 64 + (lane & 7) + (lane >> 4) * 8;
    int bCol = ((lane >> 3) & 1) * 16;

    int nk = K >> 6;
    prefetch_chunk<BM>(sb, A, B, 0, m0, n0, K, tid);
    CP_COMMIT();
    if (nk > 1) { prefetch_chunk<BM>(sb + SBYTES, A, B, 1, m0, n0, K, tid); }
    CP_COMMIT();

    for (int kc = 0; kc < nk; kc++) {
        if (kc + 2 < nk) CP_WAIT(1);
        else             CP_WAIT(0);
        __syncthreads();   // single barrier per chunk: data-ready + buffer-reuse ordering
        if (kc + 2 < nk) {
            prefetch_chunk<BM>(sb + ((kc + 2) % NSTAGE) * SBYTES, A, B, kc + 2, m0, n0, K, tid);
            CP_COMMIT();
        }

        uint32_t abase = sb + (kc % NSTAGE) * SBYTES;
        uint32_t bbase = abase + BM * 128;

        #pragma unroll
        for (int q = 0; q < 4; q++) {
            uint32_t bh[4][4];                 // 64 N-cols = 8 fragments
            #pragma unroll
            for (int gi = 0; gi < 4; gi++) {
                int r = bRow + gi * 16;
                uint32_t off = ((uint32_t)(r * 128 + q * 32 + bCol)) ^ ((uint32_t)(r & 7) << 4);
                LDSM_X4(bh[gi][0], bh[gi][1], bh[gi][2], bh[gi][3], bbase + off);
            }
            #pragma unroll
            for (int mi = 0; mi < MI; mi++) {
                int r = aRow + mi * 16;
                uint32_t off = ((uint32_t)(r * 128 + q * 32 + aCol)) ^ ((uint32_t)(r & 7) << 4);
                uint32_t ah[4];
                LDSM_X4(ah[0], ah[1], ah[2], ah[3], abase + off);
                #pragma unroll
                for (int nj = 0; nj < 8; nj++) {
                    uint32_t bf[2] = { bh[nj >> 1][(nj & 1) * 2], bh[nj >> 1][(nj & 1) * 2 + 1] };
                    MMA_F16(acc[mi][nj], ah, bf);
                }
            }
        }
    }

    float alpha = (mode == 1) ? g_alpha[g] : 0.f;

    #pragma unroll
    for (int mi = 0; mi < MI; mi++) {
        #pragma unroll
        for (int nj = 0; nj < 8; nj++) {
            int m = m0 + warpM * (BM / 2) + mi * 16 + (lane >> 2);
            int n = n0 + warpN * 64 + nj * 8 + (lane & 3) * 2;
            float c0 = acc[mi][nj][0], c1 = acc[mi][nj][1];
            float c2 = acc[mi][nj][2], c3 = acc[mi][nj][3];
            float bx = bias[n], by = bias[n + 1];
            if (mode == 1) {
                size_t coln = (size_t)g * HIDD + n;
                if (m < NN) {
                    float h0 = fast_tanh(alpha * (c0 + bx));
                    float h1 = fast_tanh(alpha * (c1 + by));
                    *(__half2*)(g_H + (size_t)m * CONCAT + coln) =
                        __halves2half2(__float2half(h0), __float2half(h1));
                }
                if (m + 8 < NN) {
                    float h2 = fast_tanh(alpha * (c2 + bx));
                    float h3 = fast_tanh(alpha * (c3 + by));
                    *(__half2*)(g_H + (size_t)(m + 8) * CONCAT + coln) =
                        __halves2half2(__float2half(h2), __float2half(h3));
                }
            } else {
                if (m < NN)
                    *(float2*)(outp + (size_t)m * OUTD + n) = make_float2(c0 + bx, c1 + by);
                if (m + 8 < NN)
                    *(float2*)(outp + (size_t)(m + 8) * OUTD + n) = make_float2(c2 + bx, c3 + by);
            }
        }
    }
}

#define SMEM1 (1024 + NSTAGE * (128 + 128) * 128)   // 99328
#define SMEM2 (1024 + NSTAGE * (64 + 128) * 128)    // 74752

// ============================================================================
// Launch
// ============================================================================
extern "C" void kernel_launch(void* const* d_in, const int* in_sizes, int n_in,
                              void* d_out, int out_size) {
    const float* x = nullptr;
    const int*   e[GG]  = {nullptr, nullptr, nullptr};
    const float* W[GG]  = {nullptr, nullptr, nullptr};
    const float* b[GG]  = {nullptr, nullptr, nullptr};
    const float* alphas = nullptr;
    const float* W_lin  = nullptr;
    const float* b_lin  = nullptr;
    int ne = 0, nw = 0, nb = 0;

    for (int i = 0; i < n_in; i++) {
        int sz = in_sizes[i];
        if      (sz == NN * IND)      x = (const float*)d_in[i];
        else if (sz == 2 * EE)        { if (ne < GG) e[ne++] = (const int*)d_in[i]; }
        else if (sz == IND * HIDD)    { if (nw < GG) W[nw++] = (const float*)d_in[i]; }
        else if (sz == HIDD)          { if (nb < GG) b[nb++] = (const float*)d_in[i]; }
        else if (sz == GG)            alphas = (const float*)d_in[i];
        else if (sz == CONCAT * OUTD) W_lin = (const float*)d_in[i];
        else if (sz == OUTD)          b_lin = (const float*)d_in[i];
    }
    float* out = (float*)d_out;

    static cudaStream_t s2 = nullptr;
    static cudaEvent_t ev_fork = nullptr, ev_join = nullptr;
    if (!s2) {
        cudaStreamCreateWithFlags(&s2, cudaStreamNonBlocking);
        cudaEventCreateWithFlags(&ev_fork, cudaEventDisableTiming);
        cudaEventCreateWithFlags(&ev_join, cudaEventDisableTiming);
    }

    cudaFuncSetAttribute((const void*)mma_gemm_kernel<128, 4>,
                         cudaFuncAttributeMaxDynamicSharedMemorySize, SMEM1);
    cudaFuncSetAttribute((const void*)mma_gemm_kernel<64, 2>,
                         cudaFuncAttributeMaxDynamicSharedMemorySize, SMEM2);

    void* degp = nullptr;
    cudaGetSymbolAddress(&degp, g_deg);
    cudaMemsetAsync(degp, 0, sizeof(int) * 2 * GG * NN, 0);

    // Fork conv onto s2 to overlap with CSR build
    cudaEventRecord(ev_fork, 0);
    cudaStreamWaitEvent(s2, ev_fork, 0);
    conv_all_kernel<<<1184, 256, 0, s2>>>(x, W[0], W[1], W[2], W_lin);

    hist_kernel<<<(GG * EE + 255) / 256, 256>>>(e[0], e[1], e[2]);
    scan_kernel<<<GG, 1024>>>(alphas);
    fill_kernel<<<(GG * EE + 255) / 256, 256>>>(e[0], e[1], e[2]);

    cudaEventRecord(ev_join, s2);
    cudaStreamWaitEvent(0, ev_join, 0);

    dim3 gridA(NN, GG);
    agg_x_kernel<<<gridA, 128>>>();

    // GEMM1: BM=128 tiles, all 3 branches in one launch (128 threads/CTA)
    int mtiles1 = (NN + 127) / 128;          // 235
    dim3 grid1(HIDD / 128, mtiles1, GG);     // 4 x 235 x 3
    mma_gemm_kernel<128, 4><<<grid1, 128, SMEM1>>>(nullptr, b[0], b[1], b[2], 1, IND);

    // GEMM2: BM=64 tiles (938 CTAs)
    int mtiles2 = (NN + 63) / 64;            // 469
    dim3 grid2(OUTD / 128, mtiles2, 1);      // 2 x 469
    mma_gemm_kernel<64, 2><<<grid2, 128, SMEM2>>>(out, b_lin, nullptr, nullptr, 2, CONCAT);
}